// round 12
// baseline (speedup 1.0000x reference)
#include <cuda_runtime.h>
#include <cuda_bf16.h>
#include <cstdint>
#include <cstddef>

#define BB    8
#define HH    8
#define NQ    1024
#define NKV   1024
#define DHD   64
#define DM    512
#define BHN   (BB*HH)

typedef unsigned long long ull;
typedef uint32_t u32;

__device__ __forceinline__ u32 smem_u32(const void* p) {
    u32 a;
    asm("{ .reg .u64 t; cvta.to.shared.u64 t, %1; cvt.u32.u64 %0, t; }" : "=r"(a) : "l"(p));
    return a;
}
__device__ __forceinline__ void ldm_x4(u32* r, u32 a) {
    asm volatile("ldmatrix.sync.aligned.m8n8.x4.shared.b16 {%0,%1,%2,%3}, [%4];"
        : "=r"(r[0]),"=r"(r[1]),"=r"(r[2]),"=r"(r[3]) : "r"(a));
}
__device__ __forceinline__ void ldm_x4t(u32* r, u32 a) {
    asm volatile("ldmatrix.sync.aligned.m8n8.x4.trans.shared.b16 {%0,%1,%2,%3}, [%4];"
        : "=r"(r[0]),"=r"(r[1]),"=r"(r[2]),"=r"(r[3]) : "r"(a));
}
__device__ __forceinline__ void mma_bf16(float* c, const u32* a, u32 b0, u32 b1) {
    asm volatile("mma.sync.aligned.m16n8k16.row.col.f32.bf16.bf16.f32 "
        "{%0,%1,%2,%3}, {%4,%5,%6,%7}, {%8,%9}, {%0,%1,%2,%3};"
        : "+f"(c[0]),"+f"(c[1]),"+f"(c[2]),"+f"(c[3])
        : "r"(a[0]),"r"(a[1]),"r"(a[2]),"r"(a[3]), "r"(b0),"r"(b1));
}
__device__ __forceinline__ void split4(float4 v, ull& hi8, ull& lo8) {
    __nv_bfloat162 h01 = __floats2bfloat162_rn(v.x, v.y);
    __nv_bfloat162 h23 = __floats2bfloat162_rn(v.z, v.w);
    float2 f01 = __bfloat1622float2(h01);
    float2 f23 = __bfloat1622float2(h23);
    __nv_bfloat162 l01 = __floats2bfloat162_rn(v.x - f01.x, v.y - f01.y);
    __nv_bfloat162 l23 = __floats2bfloat162_rn(v.z - f23.x, v.w - f23.y);
    u32 uh0 = *(u32*)&h01, uh1 = *(u32*)&h23;
    u32 ul0 = *(u32*)&l01, ul1 = *(u32*)&l23;
    hi8 = (ull)uh0 | ((ull)uh1 << 32);
    lo8 = (ull)ul0 | ((ull)ul1 << 32);
}
__device__ __forceinline__ void split2(float2 v, u32& h, u32& l) {
    __nv_bfloat162 hb = __floats2bfloat162_rn(v.x, v.y);
    float2 hf = __bfloat1622float2(hb);
    __nv_bfloat162 lb = __floats2bfloat162_rn(v.x - hf.x, v.y - hf.y);
    h = *(u32*)&hb; l = *(u32*)&lb;
}
__device__ __forceinline__ u32 pkbf(float x, float y) {
    __nv_bfloat162 t = __floats2bfloat162_rn(x, y);
    return *(u32*)&t;
}

#define CP_ASYNC16(dst, src) \
    asm volatile("cp.async.ca.shared.global [%0], [%1], 16;" :: "r"(dst), "l"(src) : "memory")
#define CP_COMMIT() asm volatile("cp.async.commit_group;" ::: "memory")
#define CP_WAIT0()  asm volatile("cp.async.wait_group 0;" ::: "memory")
#define CP_WAIT1()  asm volatile("cp.async.wait_group 1;" ::: "memory")

// ---------------- device scratch ----------------
__device__ __nv_bfloat16 g_Qhh[(size_t)BHN*NQ*DHD];
__device__ __nv_bfloat16 g_Qhl[(size_t)BHN*NQ*DHD];
__device__ __nv_bfloat16 g_Khh[(size_t)BHN*NKV*DHD];
__device__ __nv_bfloat16 g_Khl[(size_t)BHN*NKV*DHD];
__device__ __nv_bfloat16 g_Vhh[(size_t)BHN*NKV*DHD];
__device__ __nv_bfloat16 g_Vhl[(size_t)BHN*NKV*DHD];
__device__ __nv_bfloat16 g_Sb[(size_t)NQ*BHN*NKV];
__device__ __nv_bfloat16 g_qh[(size_t)BB*NQ*DM],  g_ql[(size_t)BB*NQ*DM];
__device__ __nv_bfloat16 g_kvh[(size_t)BB*NKV*DM], g_kvl[(size_t)BB*NKV*DM];
__device__ __nv_bfloat16 g_ch[(size_t)BB*NQ*DM],  g_cl[(size_t)BB*NQ*DM];
__device__ __nv_bfloat16 g_Wh[(size_t)4*DM*DM],   g_Wl[(size_t)4*DM*DM];
__device__ float g_attn_fallback[(size_t)BHN*NQ*NKV];

// =====================================================================
// cvt: fp32 -> bf16 hi/lo split
// =====================================================================
__global__ void cvt(const float* __restrict__ x,
                    __nv_bfloat16* __restrict__ h, __nv_bfloat16* __restrict__ l, int n4)
{
    int i = blockIdx.x * blockDim.x + threadIdx.x;
    if (i < n4) {
        float4 v = ((const float4*)x)[i];
        ull h8, l8; split4(v, h8, l8);
        ((ull*)h)[i] = h8;
        ((ull*)l)[i] = l8;
    }
}

// =====================================================================
// proj_body: 128x128 tile bf16 3-split GEMM (cp.async double-buffered)
// =====================================================================
#define PB_AH 0
#define PB_AL 18432
#define PB_WH 36864
#define PB_WL 54272
#define PB_STAGE 71680
#define PROJB_SMEM (2*PB_STAGE)

__device__ __forceinline__ void proj_body(
    const __nv_bfloat16* __restrict__ Ah, const __nv_bfloat16* __restrict__ Al,
    const __nv_bfloat16* __restrict__ Wh, const __nv_bfloat16* __restrict__ Wl,
    const float* __restrict__ bias, float* __restrict__ C,
    __nv_bfloat16* __restrict__ Ohi, __nv_bfloat16* __restrict__ Olo,
    int permute, char* smem, int m0, int n0)
{
    u32 sb = smem_u32(smem);
    int tid = threadIdx.x, wid = tid >> 5, lane = tid & 31;
    int wm = wid & 3, wn = wid >> 2;
    int arow = tid >> 3, ac16 = tid & 7;
    int wrow = tid >> 4, wc16 = tid & 15;

#define PB_ISSUE(kb, buf) do {                                                       \
        u32 base_ = sb + (buf) * PB_STAGE;                                           \
        _Pragma("unroll")                                                            \
        for (int r_ = 0; r_ < 4; r_++) {                                             \
            int row_ = arow + r_ * 32;                                               \
            u32 d_ = base_ + (u32)(row_ * 144 + ac16 * 16);                          \
            size_t s_ = ((size_t)(m0 + row_) * 512 + (kb) * 64 + ac16 * 8) * 2;      \
            CP_ASYNC16(d_ + PB_AH, (const char*)Ah + s_);                            \
            CP_ASYNC16(d_ + PB_AL, (const char*)Al + s_);                            \
        }                                                                            \
        _Pragma("unroll")                                                            \
        for (int r_ = 0; r_ < 4; r_++) {                                             \
            int row_ = wrow + r_ * 16;                                               \
            u32 d_ = base_ + (u32)(row_ * 272 + wc16 * 16);                          \
            size_t s_ = ((size_t)((kb) * 64 + row_) * 512 + n0 + wc16 * 8) * 2;      \
            CP_ASYNC16(d_ + PB_WH, (const char*)Wh + s_);                            \
            CP_ASYNC16(d_ + PB_WL, (const char*)Wl + s_);                            \
        }                                                                            \
        CP_COMMIT();                                                                 \
    } while (0)

    float acc[2][8][4];
#pragma unroll
    for (int m = 0; m < 2; m++)
#pragma unroll
        for (int j = 0; j < 8; j++)
#pragma unroll
            for (int t = 0; t < 4; t++) acc[m][j][t] = 0.f;

    PB_ISSUE(0, 0);
    for (int kb = 0; kb < 8; kb++) {
        if (kb < 7) { PB_ISSUE(kb + 1, (kb + 1) & 1); CP_WAIT1(); }
        else CP_WAIT0();
        __syncthreads();
        u32 base = sb + (kb & 1) * PB_STAGE;

#pragma unroll
        for (int ks = 0; ks < 4; ks++) {
            u32 ah[2][4], al[2][4];
#pragma unroll
            for (int f = 0; f < 2; f++) {
                u32 ra = base + PB_AH
                       + (u32)((wm * 32 + f * 16 + (lane & 15)) * 144 + (ks * 16 + ((lane >> 4) << 3)) * 2);
                ldm_x4(ah[f], ra);
                ldm_x4(al[f], ra + (PB_AL - PB_AH));
            }
#pragma unroll
            for (int nf = 0; nf < 4; nf++) {
                u32 rb = base + PB_WH
                       + (u32)((ks * 16 + (lane & 15)) * 272 + (wn * 64 + nf * 16 + ((lane >> 4) << 3)) * 2);
                u32 bh4[4], bl4[4];
                ldm_x4t(bh4, rb);
                ldm_x4t(bl4, rb + (PB_WL - PB_WH));
#pragma unroll
                for (int m = 0; m < 2; m++) {
                    mma_bf16(acc[m][nf*2],   ah[m], bh4[0], bh4[1]);
                    mma_bf16(acc[m][nf*2],   ah[m], bl4[0], bl4[1]);
                    mma_bf16(acc[m][nf*2],   al[m], bh4[0], bh4[1]);
                    mma_bf16(acc[m][nf*2+1], ah[m], bh4[2], bh4[3]);
                    mma_bf16(acc[m][nf*2+1], ah[m], bl4[2], bl4[3]);
                    mma_bf16(acc[m][nf*2+1], al[m], bh4[2], bh4[3]);
                }
            }
        }
        __syncthreads();
    }

    int r0 = m0 + wm * 32 + (lane >> 2);
    int cb = n0 + wn * 64 + (lane & 3) * 2;
#pragma unroll
    for (int m = 0; m < 2; m++) {
#pragma unroll
        for (int j = 0; j < 8; j++) {
            int col = cb + j * 8;
            float2 bv = *(const float2*)&bias[col];
            int rowA = r0 + m * 16, rowB = rowA + 8;
            float2 vA = make_float2(acc[m][j][0] + bv.x, acc[m][j][1] + bv.y);
            float2 vB = make_float2(acc[m][j][2] + bv.x, acc[m][j][3] + bv.y);
            if (permute) {
                int h = col >> 6, dd = col & 63;
                size_t eA = ((size_t)((rowA >> 10) * HH + h) * NQ + (rowA & 1023)) * 64 + dd;
                size_t eB = ((size_t)((rowB >> 10) * HH + h) * NQ + (rowB & 1023)) * 64 + dd;
                u32 hA, lA, hB, lB;
                split2(vA, hA, lA); split2(vB, hB, lB);
                *(u32*)((char*)Ohi + eA * 2) = hA;
                *(u32*)((char*)Olo + eA * 2) = lA;
                *(u32*)((char*)Ohi + eB * 2) = hB;
                *(u32*)((char*)Olo + eB * 2) = lB;
            } else {
                *(float2*)(C + (size_t)rowA * 512 + col) = vA;
                *(float2*)(C + (size_t)rowB * 512 + col) = vB;
            }
        }
    }
}

// fused Q/K/V projections: grid (4, 64, 3)
__global__ __launch_bounds__(256) void proj_qkv(
    const __nv_bfloat16* __restrict__ qAh, const __nv_bfloat16* __restrict__ qAl,
    const __nv_bfloat16* __restrict__ kvAh, const __nv_bfloat16* __restrict__ kvAl,
    const __nv_bfloat16* __restrict__ Wh, const __nv_bfloat16* __restrict__ Wl,
    const float* bq, const float* bk, const float* bv,
    __nv_bfloat16* Qhh, __nv_bfloat16* Qhl,
    __nv_bfloat16* Khh, __nv_bfloat16* Khl,
    __nv_bfloat16* Vhh, __nv_bfloat16* Vhl)
{
    extern __shared__ __align__(128) char smem[];
    int z = blockIdx.z;
    const size_t WSZ = (size_t)DM * DM;
    const __nv_bfloat16* Ah = z == 0 ? qAh : kvAh;
    const __nv_bfloat16* Al = z == 0 ? qAl : kvAl;
    const float* bias = z == 0 ? bq : (z == 1 ? bk : bv);
    __nv_bfloat16* Oh = z == 0 ? Qhh : (z == 1 ? Khh : Vhh);
    __nv_bfloat16* Ol = z == 0 ? Qhl : (z == 1 ? Khl : Vhl);
    proj_body(Ah, Al, Wh + z * WSZ, Wl + z * WSZ, bias, nullptr, Oh, Ol, 1,
              smem, blockIdx.y * 128, blockIdx.x * 128);
}

// output projection: grid (4, 64)
__global__ __launch_bounds__(256) void proj_o(
    const __nv_bfloat16* __restrict__ Ah, const __nv_bfloat16* __restrict__ Al,
    const __nv_bfloat16* __restrict__ Wh, const __nv_bfloat16* __restrict__ Wl,
    const float* __restrict__ bias, float* __restrict__ C)
{
    extern __shared__ __align__(128) char smem[];
    proj_body(Ah, Al, Wh, Wl, bias, C, nullptr, nullptr, 0,
              smem, blockIdx.y * 128, blockIdx.x * 128);
}

// =====================================================================
// bias_mma v4: 2-term, Q frags reloaded (low regs), occ 3.
// =====================================================================
#define BZ_RH 0
#define BZ_QH 36864
#define BZ_QL 46080
#define BIAS_SMEM 55296

__global__ __launch_bounds__(256, 3) void bias_mma(
    const __nv_bfloat16* __restrict__ Qhh, const __nv_bfloat16* __restrict__ Qhl,
    const float* __restrict__ R, __nv_bfloat16* __restrict__ Sb)
{
    extern __shared__ __align__(128) char smem[];
    u32 sb = smem_u32(smem);
    int tid = threadIdx.x, wid = tid >> 5, lane = tid & 31;
    int wm = wid & 3, wn = wid >> 2;
    int q = blockIdx.y, kc = blockIdx.x;

#pragma unroll
    for (int r = 0; r < 2; r++) {
        int idx = tid + r * 256;
        int row = idx >> 3, c4 = idx & 7;
        u32 off = (u32)(row * 144 + c4 * 16);
        size_t e = ((size_t)row * NQ + q) * DHD + c4 * 8;
        *(uint4*)(smem + BZ_QH + off) = *(const uint4*)((const char*)Qhh + e * 2);
        *(uint4*)(smem + BZ_QL + off) = *(const uint4*)((const char*)Qhl + e * 2);
    }
    __syncthreads();

    for (int kt = 0; kt < 4; kt++) {
        int k0 = (kc * 4 + kt) * 128;
#pragma unroll
        for (int r = 0; r < 8; r++) {
            int idx = tid + r * 256;
            int row = idx >> 4, col = (idx & 15) << 2;
            float4 v = *(const float4*)(R + ((size_t)q * NKV + k0 + row) * DHD + col);
            u32 p0 = pkbf(v.x, v.y), p1 = pkbf(v.z, v.w);
            *(ull*)(smem + BZ_RH + (row * 72 + col) * 2) = (ull)p0 | ((ull)p1 << 32);
        }
        __syncthreads();

        float acc[2][4][4];
#pragma unroll
        for (int m = 0; m < 2; m++)
#pragma unroll
            for (int j = 0; j < 4; j++)
#pragma unroll
                for (int t = 0; t < 4; t++) acc[m][j][t] = 0.f;

#pragma unroll
        for (int ks = 0; ks < 4; ks++) {
            u32 ah[2][4];
#pragma unroll
            for (int f = 0; f < 2; f++) {
                u32 ra = (u32)((wm * 32 + f * 16 + (lane & 15)) * 72 + ks * 16 + ((lane >> 4) << 3)) * 2;
                ldm_x4(ah[f], sb + BZ_RH + ra);
            }
#pragma unroll
            for (int g = 0; g < 2; g++) {
                u32 rb = (u32)((wn * 32 + g * 16 + (lane & 7) + ((lane >> 4) << 3)) * 72
                               + ks * 16 + (((lane >> 3) & 1) << 3)) * 2;
                u32 qh4[4], ql4[4];
                ldm_x4(qh4, sb + BZ_QH + rb);
                ldm_x4(ql4, sb + BZ_QL + rb);
#pragma unroll
                for (int m = 0; m < 2; m++) {
                    mma_bf16(acc[m][g*2],   ah[m], qh4[0], qh4[1]);
                    mma_bf16(acc[m][g*2],   ah[m], ql4[0], ql4[1]);
                    mma_bf16(acc[m][g*2+1], ah[m], qh4[2], qh4[3]);
                    mma_bf16(acc[m][g*2+1], ah[m], ql4[2], ql4[3]);
                }
            }
        }
        __syncthreads();

        float* T = (float*)smem;
#pragma unroll
        for (int m = 0; m < 2; m++) {
            int krow = wm * 32 + m * 16 + (lane >> 2);
#pragma unroll
            for (int j = 0; j < 4; j++) {
                int bhc = wn * 32 + j * 8 + (lane & 3) * 2;
                T[bhc * 132 + krow]           = acc[m][j][0];
                T[(bhc + 1) * 132 + krow]     = acc[m][j][1];
                T[bhc * 132 + krow + 8]       = acc[m][j][2];
                T[(bhc + 1) * 132 + krow + 8] = acc[m][j][3];
            }
        }
        __syncthreads();

        int bh2 = tid >> 2, part = tid & 3;
        size_t dbase = ((size_t)q * BHN + bh2) * NKV + k0 + part * 32;
#pragma unroll
        for (int j = 0; j < 4; j++) {
            float4 a = *(float4*)&T[bh2 * 132 + part * 32 + j * 8];
            float4 b = *(float4*)&T[bh2 * 132 + part * 32 + j * 8 + 4];
            uint4 o;
            o.x = pkbf(a.x, a.y); o.y = pkbf(a.z, a.w);
            o.z = pkbf(b.x, b.y); o.w = pkbf(b.z, b.w);
            *(uint4*)((char*)Sb + (dbase + j * 8) * 2) = o;
        }
        __syncthreads();
    }
}

// =====================================================================
// attn_mma: unchanged (round-11, passing).
// =====================================================================
#define SROW  1028
#define AS_MB 65792
#define AS_QH 69888
#define AS_QL 72192
#define AS_KB 74496
#define KLO   18432
#define ATTN_SMEM 111360

__global__ __launch_bounds__(256, 2) void attn_mma(
    const __nv_bfloat16* __restrict__ Qhh, const __nv_bfloat16* __restrict__ Qhl,
    const __nv_bfloat16* __restrict__ Khh, const __nv_bfloat16* __restrict__ Khl,
    const __nv_bfloat16* __restrict__ Vhh, const __nv_bfloat16* __restrict__ Vhl,
    const __nv_bfloat16* __restrict__ Sb,
    const int* __restrict__ mask, float* __restrict__ attn,
    __nv_bfloat16* __restrict__ Ch, __nv_bfloat16* __restrict__ Cl)
{
    extern __shared__ __align__(128) char smem[];
    u32 sbp = smem_u32(smem);
    float* S  = (float*)smem;
    float* mb = (float*)(smem + AS_MB);
    int tid = threadIdx.x, wid = tid >> 5, lane = tid & 31;
    int bh  = blockIdx.x;
    int q0  = blockIdx.y * 16;
    int b = bh >> 3, h = bh & 7;
    const float scale = 0.125f;

    const __nv_bfloat16* KhB = Khh + (size_t)bh * NKV * DHD;
    const __nv_bfloat16* KlB = Khl + (size_t)bh * NKV * DHD;
    const __nv_bfloat16* VhB = Vhh + (size_t)bh * NKV * DHD;
    const __nv_bfloat16* VlB = Vhl + (size_t)bh * NKV * DHD;

    if (tid < 128) {
        int row = tid >> 3, c4 = tid & 7;
        u32 off = (u32)(row * 144 + c4 * 16);
        size_t e = ((size_t)bh * NQ + q0 + row) * DHD + c4 * 8;
        *(uint4*)(smem + AS_QH + off) = *(const uint4*)((const char*)Qhh + e * 2);
        *(uint4*)(smem + AS_QL + off) = *(const uint4*)((const char*)Qhl + e * 2);
    }
    for (int k = tid; k < NKV; k += 256)
        mb[k] = mask[b * NKV + k] ? 0.f : -1e30f;
    __syncthreads();

    u32 qh[4][4], ql[4][4];
#pragma unroll
    for (int ds = 0; ds < 4; ds++) {
        u32 ra = (u32)((lane & 15) * 72 + ds * 16 + ((lane >> 4) << 3)) * 2;
        ldm_x4(qh[ds], sbp + AS_QH + ra);
        ldm_x4(ql[ds], sbp + AS_QL + ra);
    }

    int prow = tid >> 3, pc4 = tid & 7;
    u32 poff0 = (u32)(prow * 144 + pc4 * 16);
    size_t psrc0 = (size_t)prow * 64 + pc4 * 8;

#define ISSUE_CHUNK(HIptr, LOptr, cix) do {                                        \
        u32 dh_ = sbp + AS_KB;                                                     \
        u32 dl_ = dh_ + KLO;                                                       \
        const char* sh_ = (const char*)((HIptr) + (size_t)(cix) * 128 * 64);       \
        const char* sl_ = (const char*)((LOptr) + (size_t)(cix) * 128 * 64);       \
        _Pragma("unroll")                                                          \
        for (int r_ = 0; r_ < 4; r_++) {                                           \
            u32 o_ = poff0 + (u32)r_ * 32 * 144;                                   \
            size_t s_ = (psrc0 + (size_t)r_ * 32 * 64) * 2;                        \
            CP_ASYNC16(dh_ + o_, sh_ + s_);                                        \
            CP_ASYNC16(dl_ + o_, sl_ + s_);                                        \
        }                                                                          \
        CP_COMMIT();                                                               \
    } while (0)

    // ---- Phase 1: QK^T + Sb + mask ----
    for (int c = 0; c < 8; c++) {
        ISSUE_CHUNK(KhB, KlB, c);
        CP_WAIT0();
        __syncthreads();
        u32 bufH = sbp + AS_KB, bufL = bufH + KLO;

        float acc[2][4];
#pragma unroll
        for (int j = 0; j < 2; j++)
#pragma unroll
            for (int t = 0; t < 4; t++) acc[j][t] = 0.f;

#pragma unroll
        for (int ds = 0; ds < 4; ds++) {
            u32 rb = (u32)((wid * 16 + (lane & 15)) * 72 + ds * 16 + ((lane >> 4) << 3)) * 2;
            u32 kh4[4], kl4[4];
            ldm_x4(kh4, bufH + rb);
            ldm_x4(kl4, bufL + rb);
            mma_bf16(acc[0], qh[ds], kh4[0], kh4[2]);
            mma_bf16(acc[0], qh[ds], kl4[0], kl4[2]);
            mma_bf16(acc[0], ql[ds], kh4[0], kh4[2]);
            mma_bf16(acc[1], qh[ds], kh4[1], kh4[3]);
            mma_bf16(acc[1], qh[ds], kl4[1], kl4[3]);
            mma_bf16(acc[1], ql[ds], kh4[1], kh4[3]);
        }
        int qq = lane >> 2;
#pragma unroll
        for (int j = 0; j < 2; j++) {
            int k = c * 128 + wid * 16 + j * 8 + (lane & 3) * 2;
            u32 u0 = *(const u32*)((const char*)Sb + (((size_t)(q0 + qq) * BHN + bh) * NKV + k) * 2);
            u32 u1 = *(const u32*)((const char*)Sb + (((size_t)(q0 + qq + 8) * BHN + bh) * NKV + k) * 2);
            float2 b0 = __bfloat1622float2(*(__nv_bfloat162*)&u0);
            float2 b1 = __bfloat1622float2(*(__nv_bfloat162*)&u1);
            float2 mm = *(const float2*)&mb[k];
            *(float2*)&S[qq * SROW + k] = make_float2(
                (acc[j][0] + b0.x) * scale + mm.x,
                (acc[j][1] + b0.y) * scale + mm.y);
            *(float2*)&S[(qq + 8) * SROW + k] = make_float2(
                (acc[j][2] + b1.x) * scale + mm.x,
                (acc[j][3] + b1.y) * scale + mm.y);
        }
        __syncthreads();
    }

    // ---- Phase 2: softmax + attn store ----
    for (int r = 0; r < 2; r++) {
        float* row = S + (wid * 2 + r) * SROW;
        float m = -3.4e38f;
        for (int k = lane; k < NKV; k += 32) m = fmaxf(m, row[k]);
#pragma unroll
        for (int o = 16; o; o >>= 1) m = fmaxf(m, __shfl_xor_sync(0xffffffffu, m, o));
        float s = 0.f;
        for (int k = lane; k < NKV; k += 32) {
            float e = __expf(row[k] - m);
            row[k] = e; s += e;
        }
#pragma unroll
        for (int o = 16; o; o >>= 1) s += __shfl_xor_sync(0xffffffffu, s, o);
        float inv = 1.f / s;
        __syncwarp();
        float* arow = attn + ((size_t)bh * NQ + q0 + wid * 2 + r) * NKV;
        for (int k = lane * 4; k < NKV; k += 128) {
            float4 v = *(float4*)&row[k];
            v.x *= inv; v.y *= inv; v.z *= inv; v.w *= inv;
            *(float4*)&row[k] = v;
            *(float4*)&arow[k] = v;
        }
        __syncwarp();
    }
    __syncthreads();

    // ---- Phase 3: ctx = P @ V ----
    float acc[8][4];
#pragma unroll
    for (int j = 0; j < 8; j++)
#pragma unroll
        for (int t = 0; t < 4; t++) acc[j][t] = 0.f;

    for (int c = 0; c < 8; c++) {
        ISSUE_CHUNK(VhB, VlB, c);
        CP_WAIT0();
        __syncthreads();
        u32 bufH = sbp + AS_KB, bufL = bufH + KLO;
        int kbase = c * 128 + wid * 16;

        u32 ph[4], pl[4];
        {
            int r0 = lane >> 2;
            const float* Sr0 = S + r0 * SROW;
            const float* Sr1 = S + (r0 + 8) * SROW;
            int cc = kbase + (lane & 3) * 2;
            split2(*(const float2*)(Sr0 + cc),     ph[0], pl[0]);
            split2(*(const float2*)(Sr1 + cc),     ph[1], pl[1]);
            split2(*(const float2*)(Sr0 + cc + 8), ph[2], pl[2]);
            split2(*(const float2*)(Sr1 + cc + 8), ph[3], pl[3]);
        }
#pragma unroll
        for (int dn = 0; dn < 4; dn++) {
            u32 rv = (u32)((wid * 16 + (lane & 15)) * 72 + dn * 16 + ((lane >> 4) << 3)) * 2;
            u32 vh4[4], vl4[4];
            ldm_x4t(vh4, bufH + rv);
            ldm_x4t(vl4, bufL + rv);
            mma_bf16(acc[dn*2],   ph, vh4[0], vh4[1]);
            mma_bf16(acc[dn*2],   ph, vl4[0], vl4[1]);
            mma_bf16(acc[dn*2],   pl, vh4[0], vh4[1]);
            mma_bf16(acc[dn*2+1], ph, vh4[2], vh4[3]);
            mma_bf16(acc[dn*2+1], ph, vl4[2], vl4[3]);
            mma_bf16(acc[dn*2+1], pl, vh4[2], vh4[3]);
        }
        __syncthreads();
    }

    float* slab = (float*)(smem + AS_KB);
    {
        int qq = lane >> 2;
#pragma unroll
        for (int j = 0; j < 8; j++) {
            int d = j * 8 + (lane & 3) * 2;
            *(float2*)&slab[(wid * 16 + qq) * 68 + d]     = make_float2(acc[j][0], acc[j][1]);
            *(float2*)&slab[(wid * 16 + qq + 8) * 68 + d] = make_float2(acc[j][2], acc[j][3]);
        }
    }
    __syncthreads();

    {
        int qq = tid >> 4, db = (tid & 15) * 4;
        float s[4] = {0.f, 0.f, 0.f, 0.f};
#pragma unroll
        for (int w = 0; w < 8; w++) {
            const float* p = &slab[(w * 16 + qq) * 68 + db];
#pragma unroll
            for (int t = 0; t < 4; t++) s[t] += p[t];
        }
        size_t e = ((size_t)b * NQ + q0 + qq) * DM + h * DHD + db;
        u32 h0, l0, h1, l1;
        split2(make_float2(s[0], s[1]), h0, l0);
        split2(make_float2(s[2], s[3]), h1, l1);
        *(u32*)((char*)Ch + e * 2)     = h0;
        *(u32*)((char*)Ch + e * 2 + 4) = h1;
        *(u32*)((char*)Cl + e * 2)     = l0;
        *(u32*)((char*)Cl + e * 2 + 4) = l1;
    }
}

// =====================================================================
// launcher
// =====================================================================
extern "C" void kernel_launch(void* const* d_in, const int* in_sizes, int n_in,
                              void* d_out, int out_size)
{
    const float* q    = (const float*)d_in[0];
    const float* kv   = (const float*)d_in[1];
    const int*   mask = (const int*)  d_in[2];
    const float* Wq   = (const float*)d_in[3];
    const float* bq   = (const float*)d_in[4];
    const float* Wk   = (const float*)d_in[5];
    const float* bk   = (const float*)d_in[6];
    const float* Wv   = (const float*)d_in[7];
    const float* bv   = (const float*)d_in[8];
    const float* Wo   = (const float*)d_in[9];
    const float* bo   = (const float*)d_in[10];
    const float* R    = (const float*)d_in[11];

    float* out = (float*)d_out;
    const size_t out_elems  = (size_t)BB*NQ*DM;
    const size_t attn_elems = (size_t)BHN*NQ*NKV;

    __nv_bfloat16 *Qhh, *Qhl, *Khh, *Khl, *Vhh, *Vhl, *Sb;
    __nv_bfloat16 *qh, *ql2, *kvh, *kvl, *ch, *cl, *Wh, *Wl;
    float *attn_fb;
    cudaGetSymbolAddress((void**)&Qhh, g_Qhh);
    cudaGetSymbolAddress((void**)&Qhl, g_Qhl);
    cudaGetSymbolAddress((void**)&Khh, g_Khh);
    cudaGetSymbolAddress((void**)&Khl, g_Khl);
    cudaGetSymbolAddress((void**)&Vhh, g_Vhh);
    cudaGetSymbolAddress((void**)&Vhl, g_Vhl);
    cudaGetSymbolAddress((void**)&Sb,  g_Sb);
    cudaGetSymbolAddress((void**)&qh,  g_qh);
    cudaGetSymbolAddress((void**)&ql2, g_ql);
    cudaGetSymbolAddress((void**)&kvh, g_kvh);
    cudaGetSymbolAddress((void**)&kvl, g_kvl);
    cudaGetSymbolAddress((void**)&ch,  g_ch);
    cudaGetSymbolAddress((void**)&cl,  g_cl);
    cudaGetSymbolAddress((void**)&Wh,  g_Wh);
    cudaGetSymbolAddress((void**)&Wl,  g_Wl);
    cudaGetSymbolAddress((void**)&attn_fb, g_attn_fallback);

    float* attn = ((size_t)out_size >= out_elems + attn_elems)
                ? (out + out_elems) : attn_fb;

    cudaFuncSetAttribute(proj_qkv, cudaFuncAttributeMaxDynamicSharedMemorySize, PROJB_SMEM);
    cudaFuncSetAttribute(proj_o,   cudaFuncAttributeMaxDynamicSharedMemorySize, PROJB_SMEM);
    cudaFuncSetAttribute(bias_mma, cudaFuncAttributeMaxDynamicSharedMemorySize, BIAS_SMEM);
    cudaFuncSetAttribute(attn_mma, cudaFuncAttributeMaxDynamicSharedMemorySize, ATTN_SMEM);

    const size_t WSZ = (size_t)DM * DM;
    cvt<<<4096, 256>>>(q,  qh,  ql2, (int)(out_elems / 4));
    cvt<<<4096, 256>>>(kv, kvh, kvl, (int)(out_elems / 4));
    cvt<<<256, 256>>>(Wq, Wh + 0*WSZ, Wl + 0*WSZ, (int)(WSZ / 4));
    cvt<<<256, 256>>>(Wk, Wh + 1*WSZ, Wl + 1*WSZ, (int)(WSZ / 4));
    cvt<<<256, 256>>>(Wv, Wh + 2*WSZ, Wl + 2*WSZ, (int)(WSZ / 4));
    cvt<<<256, 256>>>(Wo, Wh + 3*WSZ, Wl + 3*WSZ, (int)(WSZ / 4));

    proj_qkv<<<dim3(4, 64, 3), 256, PROJB_SMEM>>>(qh, ql2, kvh, kvl, Wh, Wl,
                                                  bq, bk, bv,
                                                  Qhh, Qhl, Khh, Khl, Vhh, Vhl);

    bias_mma<<<dim3(2, 1024), 256, BIAS_SMEM>>>(Qhh, Qhl, R, Sb);

    attn_mma<<<dim3(64, 64), 256, ATTN_SMEM>>>(Qhh, Qhl, Khh, Khl, Vhh, Vhl,
                                               Sb, mask, attn, ch, cl);

    proj_o<<<dim3(4, 64), 256, PROJB_SMEM>>>(ch, cl, Wh + 3*WSZ, Wl + 3*WSZ, bo, out);
}

// round 13
// speedup vs baseline: 1.0117x; 1.0117x over previous
#include <cuda_runtime.h>
#include <cuda_bf16.h>
#include <cstdint>
#include <cstddef>

#define BB    8
#define HH    8
#define NQ    1024
#define NKV   1024
#define DHD   64
#define DM    512
#define BHN   (BB*HH)

typedef unsigned long long ull;
typedef uint32_t u32;

__device__ __forceinline__ u32 smem_u32(const void* p) {
    u32 a;
    asm("{ .reg .u64 t; cvta.to.shared.u64 t, %1; cvt.u32.u64 %0, t; }" : "=r"(a) : "l"(p));
    return a;
}
__device__ __forceinline__ void ldm_x4(u32* r, u32 a) {
    asm volatile("ldmatrix.sync.aligned.m8n8.x4.shared.b16 {%0,%1,%2,%3}, [%4];"
        : "=r"(r[0]),"=r"(r[1]),"=r"(r[2]),"=r"(r[3]) : "r"(a));
}
__device__ __forceinline__ void ldm_x4t(u32* r, u32 a) {
    asm volatile("ldmatrix.sync.aligned.m8n8.x4.trans.shared.b16 {%0,%1,%2,%3}, [%4];"
        : "=r"(r[0]),"=r"(r[1]),"=r"(r[2]),"=r"(r[3]) : "r"(a));
}
__device__ __forceinline__ void mma_bf16(float* c, const u32* a, u32 b0, u32 b1) {
    asm volatile("mma.sync.aligned.m16n8k16.row.col.f32.bf16.bf16.f32 "
        "{%0,%1,%2,%3}, {%4,%5,%6,%7}, {%8,%9}, {%0,%1,%2,%3};"
        : "+f"(c[0]),"+f"(c[1]),"+f"(c[2]),"+f"(c[3])
        : "r"(a[0]),"r"(a[1]),"r"(a[2]),"r"(a[3]), "r"(b0),"r"(b1));
}
__device__ __forceinline__ void split4(float4 v, ull& hi8, ull& lo8) {
    __nv_bfloat162 h01 = __floats2bfloat162_rn(v.x, v.y);
    __nv_bfloat162 h23 = __floats2bfloat162_rn(v.z, v.w);
    float2 f01 = __bfloat1622float2(h01);
    float2 f23 = __bfloat1622float2(h23);
    __nv_bfloat162 l01 = __floats2bfloat162_rn(v.x - f01.x, v.y - f01.y);
    __nv_bfloat162 l23 = __floats2bfloat162_rn(v.z - f23.x, v.w - f23.y);
    u32 uh0 = *(u32*)&h01, uh1 = *(u32*)&h23;
    u32 ul0 = *(u32*)&l01, ul1 = *(u32*)&l23;
    hi8 = (ull)uh0 | ((ull)uh1 << 32);
    lo8 = (ull)ul0 | ((ull)ul1 << 32);
}
__device__ __forceinline__ void split2(float2 v, u32& h, u32& l) {
    __nv_bfloat162 hb = __floats2bfloat162_rn(v.x, v.y);
    float2 hf = __bfloat1622float2(hb);
    __nv_bfloat162 lb = __floats2bfloat162_rn(v.x - hf.x, v.y - hf.y);
    h = *(u32*)&hb; l = *(u32*)&lb;
}
__device__ __forceinline__ u32 pkbf(float x, float y) {
    __nv_bfloat162 t = __floats2bfloat162_rn(x, y);
    return *(u32*)&t;
}

#define CP_ASYNC16(dst, src) \
    asm volatile("cp.async.ca.shared.global [%0], [%1], 16;" :: "r"(dst), "l"(src) : "memory")
#define CP_COMMIT() asm volatile("cp.async.commit_group;" ::: "memory")
#define CP_WAIT0()  asm volatile("cp.async.wait_group 0;" ::: "memory")
#define CP_WAIT1()  asm volatile("cp.async.wait_group 1;" ::: "memory")

// ---------------- device scratch ----------------
__device__ __nv_bfloat16 g_Qhh[(size_t)BHN*NQ*DHD];
__device__ __nv_bfloat16 g_Qhl[(size_t)BHN*NQ*DHD];
__device__ __nv_bfloat16 g_Khh[(size_t)BHN*NKV*DHD];
__device__ __nv_bfloat16 g_Khl[(size_t)BHN*NKV*DHD];
__device__ __nv_bfloat16 g_Vhh[(size_t)BHN*NKV*DHD];
__device__ __nv_bfloat16 g_Vhl[(size_t)BHN*NKV*DHD];
__device__ __nv_bfloat16 g_Sb[(size_t)NQ*BHN*NKV];
__device__ __nv_bfloat16 g_qh[(size_t)BB*NQ*DM],  g_ql[(size_t)BB*NQ*DM];
__device__ __nv_bfloat16 g_kvh[(size_t)BB*NKV*DM], g_kvl[(size_t)BB*NKV*DM];
__device__ __nv_bfloat16 g_ch[(size_t)BB*NQ*DM],  g_cl[(size_t)BB*NQ*DM];
__device__ __nv_bfloat16 g_Wh[(size_t)4*DM*DM],   g_Wl[(size_t)4*DM*DM];
__device__ float g_attn_fallback[(size_t)BHN*NQ*NKV];

// =====================================================================
// cvt: fp32 -> bf16 hi/lo split
// =====================================================================
__global__ void cvt(const float* __restrict__ x,
                    __nv_bfloat16* __restrict__ h, __nv_bfloat16* __restrict__ l, int n4)
{
    int i = blockIdx.x * blockDim.x + threadIdx.x;
    if (i < n4) {
        float4 v = ((const float4*)x)[i];
        ull h8, l8; split4(v, h8, l8);
        ((ull*)h)[i] = h8;
        ((ull*)l)[i] = l8;
    }
}

// =====================================================================
// proj_bf v2: K-chunks of 32, double-buffered, 2 CTAs/SM.
// stage: AH [128][80B] AL +10240  WH [32][272B] +20480  WL +29184
// stage = 37888 B, total 75776 B -> occupancy 2.
// =====================================================================
#define PB_AH 0
#define PB_AL 10240
#define PB_WH 20480
#define PB_WL 29184
#define PB_STAGE 37888
#define PROJB_SMEM (2*PB_STAGE)

__global__ __launch_bounds__(256, 2) void proj_bf(
    const __nv_bfloat16* __restrict__ Ah, const __nv_bfloat16* __restrict__ Al,
    const __nv_bfloat16* __restrict__ Wh, const __nv_bfloat16* __restrict__ Wl,
    const float* __restrict__ bias, float* __restrict__ C,
    __nv_bfloat16* __restrict__ Ohi, __nv_bfloat16* __restrict__ Olo,
    int permute)
{
    extern __shared__ __align__(128) char smem[];
    u32 sb = smem_u32(smem);
    int tid = threadIdx.x, wid = tid >> 5, lane = tid & 31;
    int m0 = blockIdx.y * 128, n0 = blockIdx.x * 128;
    int wm = wid & 3, wn = wid >> 2;

    int arow = tid >> 2, ac = tid & 3;        // A copy: 64 rows/iter x 4 c16
    int wrow = tid >> 4, wc16 = tid & 15;     // W copy: 16 rows/iter x 16 c16

#define PB_ISSUE(kb, buf) do {                                                       \
        u32 base_ = sb + (buf) * PB_STAGE;                                           \
        _Pragma("unroll")                                                            \
        for (int r_ = 0; r_ < 2; r_++) {                                             \
            int row_ = arow + r_ * 64;                                               \
            u32 d_ = base_ + (u32)(row_ * 80 + ac * 16);                             \
            size_t s_ = ((size_t)(m0 + row_) * 512 + (kb) * 32 + ac * 8) * 2;        \
            CP_ASYNC16(d_ + PB_AH, (const char*)Ah + s_);                            \
            CP_ASYNC16(d_ + PB_AL, (const char*)Al + s_);                            \
        }                                                                            \
        _Pragma("unroll")                                                            \
        for (int r_ = 0; r_ < 2; r_++) {                                             \
            int row_ = wrow + r_ * 16;                                               \
            u32 d_ = base_ + (u32)(row_ * 272 + wc16 * 16);                          \
            size_t s_ = ((size_t)((kb) * 32 + row_) * 512 + n0 + wc16 * 8) * 2;      \
            CP_ASYNC16(d_ + PB_WH, (const char*)Wh + s_);                            \
            CP_ASYNC16(d_ + PB_WL, (const char*)Wl + s_);                            \
        }                                                                            \
        CP_COMMIT();                                                                 \
    } while (0)

    float acc[2][8][4];
#pragma unroll
    for (int m = 0; m < 2; m++)
#pragma unroll
        for (int j = 0; j < 8; j++)
#pragma unroll
            for (int t = 0; t < 4; t++) acc[m][j][t] = 0.f;

    PB_ISSUE(0, 0);
    for (int kb = 0; kb < 16; kb++) {
        if (kb < 15) { PB_ISSUE(kb + 1, (kb + 1) & 1); CP_WAIT1(); }
        else CP_WAIT0();
        __syncthreads();
        u32 base = sb + (kb & 1) * PB_STAGE;

#pragma unroll
        for (int ks = 0; ks < 2; ks++) {
            u32 ah[2][4], al[2][4];
#pragma unroll
            for (int f = 0; f < 2; f++) {
                u32 ra = base + PB_AH
                       + (u32)((wm * 32 + f * 16 + (lane & 15)) * 80 + (ks * 16 + ((lane >> 4) << 3)) * 2);
                ldm_x4(ah[f], ra);
                ldm_x4(al[f], ra + (PB_AL - PB_AH));
            }
#pragma unroll
            for (int nf = 0; nf < 4; nf++) {
                u32 rb = base + PB_WH
                       + (u32)((ks * 16 + (lane & 15)) * 272 + (wn * 64 + nf * 16 + ((lane >> 4) << 3)) * 2);
                u32 bh4[4], bl4[4];
                ldm_x4t(bh4, rb);
                ldm_x4t(bl4, rb + (PB_WL - PB_WH));
#pragma unroll
                for (int m = 0; m < 2; m++) {
                    mma_bf16(acc[m][nf*2],   ah[m], bh4[0], bh4[1]);
                    mma_bf16(acc[m][nf*2],   ah[m], bl4[0], bl4[1]);
                    mma_bf16(acc[m][nf*2],   al[m], bh4[0], bh4[1]);
                    mma_bf16(acc[m][nf*2+1], ah[m], bh4[2], bh4[3]);
                    mma_bf16(acc[m][nf*2+1], ah[m], bl4[2], bl4[3]);
                    mma_bf16(acc[m][nf*2+1], al[m], bh4[2], bh4[3]);
                }
            }
        }
        __syncthreads();
    }

    int r0 = m0 + wm * 32 + (lane >> 2);
    int cb = n0 + wn * 64 + (lane & 3) * 2;
#pragma unroll
    for (int m = 0; m < 2; m++) {
#pragma unroll
        for (int j = 0; j < 8; j++) {
            int col = cb + j * 8;
            float2 bv = *(const float2*)&bias[col];
            int rowA = r0 + m * 16, rowB = rowA + 8;
            float2 vA = make_float2(acc[m][j][0] + bv.x, acc[m][j][1] + bv.y);
            float2 vB = make_float2(acc[m][j][2] + bv.x, acc[m][j][3] + bv.y);
            if (permute) {
                int h = col >> 6, dd = col & 63;
                size_t eA = ((size_t)((rowA >> 10) * HH + h) * NQ + (rowA & 1023)) * 64 + dd;
                size_t eB = ((size_t)((rowB >> 10) * HH + h) * NQ + (rowB & 1023)) * 64 + dd;
                u32 hA, lA, hB, lB;
                split2(vA, hA, lA); split2(vB, hB, lB);
                *(u32*)((char*)Ohi + eA * 2) = hA;
                *(u32*)((char*)Olo + eA * 2) = lA;
                *(u32*)((char*)Ohi + eB * 2) = hB;
                *(u32*)((char*)Olo + eB * 2) = lB;
            } else {
                *(float2*)(C + (size_t)rowA * 512 + col) = vA;
                *(float2*)(C + (size_t)rowB * 512 + col) = vB;
            }
        }
    }
}

// =====================================================================
// bias_mma: round-11 version (2-term, Q frags hoisted). grid (2, 1024).
// =====================================================================
#define BZ_RH 0
#define BZ_QH 36864
#define BZ_QL 46080
#define BIAS_SMEM 55296

__global__ __launch_bounds__(256) void bias_mma(
    const __nv_bfloat16* __restrict__ Qhh, const __nv_bfloat16* __restrict__ Qhl,
    const float* __restrict__ R, __nv_bfloat16* __restrict__ Sb)
{
    extern __shared__ __align__(128) char smem[];
    u32 sb = smem_u32(smem);
    int tid = threadIdx.x, wid = tid >> 5, lane = tid & 31;
    int wm = wid & 3, wn = wid >> 2;
    int q = blockIdx.y, kc = blockIdx.x;

#pragma unroll
    for (int r = 0; r < 2; r++) {
        int idx = tid + r * 256;
        int row = idx >> 3, c4 = idx & 7;
        u32 off = (u32)(row * 144 + c4 * 16);
        size_t e = ((size_t)row * NQ + q) * DHD + c4 * 8;
        *(uint4*)(smem + BZ_QH + off) = *(const uint4*)((const char*)Qhh + e * 2);
        *(uint4*)(smem + BZ_QL + off) = *(const uint4*)((const char*)Qhl + e * 2);
    }
    __syncthreads();

    u32 qh4[4][2][4], ql4[4][2][4];
#pragma unroll
    for (int ks = 0; ks < 4; ks++)
#pragma unroll
        for (int g = 0; g < 2; g++) {
            u32 rb = (u32)((wn * 32 + g * 16 + (lane & 7) + ((lane >> 4) << 3)) * 72
                           + ks * 16 + (((lane >> 3) & 1) << 3)) * 2;
            ldm_x4(qh4[ks][g], sb + BZ_QH + rb);
            ldm_x4(ql4[ks][g], sb + BZ_QL + rb);
        }

    for (int kt = 0; kt < 4; kt++) {
        int k0 = (kc * 4 + kt) * 128;
#pragma unroll
        for (int r = 0; r < 8; r++) {
            int idx = tid + r * 256;
            int row = idx >> 4, col = (idx & 15) << 2;
            float4 v = *(const float4*)(R + ((size_t)q * NKV + k0 + row) * DHD + col);
            u32 p0 = pkbf(v.x, v.y), p1 = pkbf(v.z, v.w);
            *(ull*)(smem + BZ_RH + (row * 72 + col) * 2) = (ull)p0 | ((ull)p1 << 32);
        }
        __syncthreads();

        float acc[2][4][4];
#pragma unroll
        for (int m = 0; m < 2; m++)
#pragma unroll
            for (int j = 0; j < 4; j++)
#pragma unroll
                for (int t = 0; t < 4; t++) acc[m][j][t] = 0.f;

#pragma unroll
        for (int ks = 0; ks < 4; ks++) {
            u32 ah[2][4];
#pragma unroll
            for (int f = 0; f < 2; f++) {
                u32 ra = (u32)((wm * 32 + f * 16 + (lane & 15)) * 72 + ks * 16 + ((lane >> 4) << 3)) * 2;
                ldm_x4(ah[f], sb + BZ_RH + ra);
            }
#pragma unroll
            for (int g = 0; g < 2; g++)
#pragma unroll
                for (int m = 0; m < 2; m++) {
                    mma_bf16(acc[m][g*2],   ah[m], qh4[ks][g][0], qh4[ks][g][1]);
                    mma_bf16(acc[m][g*2],   ah[m], ql4[ks][g][0], ql4[ks][g][1]);
                    mma_bf16(acc[m][g*2+1], ah[m], qh4[ks][g][2], qh4[ks][g][3]);
                    mma_bf16(acc[m][g*2+1], ah[m], ql4[ks][g][2], ql4[ks][g][3]);
                }
        }
        __syncthreads();

        float* T = (float*)smem;
#pragma unroll
        for (int m = 0; m < 2; m++) {
            int krow = wm * 32 + m * 16 + (lane >> 2);
#pragma unroll
            for (int j = 0; j < 4; j++) {
                int bhc = wn * 32 + j * 8 + (lane & 3) * 2;
                T[bhc * 132 + krow]           = acc[m][j][0];
                T[(bhc + 1) * 132 + krow]     = acc[m][j][1];
                T[bhc * 132 + krow + 8]       = acc[m][j][2];
                T[(bhc + 1) * 132 + krow + 8] = acc[m][j][3];
            }
        }
        __syncthreads();

        int bh2 = tid >> 2, part = tid & 3;
        size_t dbase = ((size_t)q * BHN + bh2) * NKV + k0 + part * 32;
#pragma unroll
        for (int j = 0; j < 4; j++) {
            float4 a = *(float4*)&T[bh2 * 132 + part * 32 + j * 8];
            float4 b = *(float4*)&T[bh2 * 132 + part * 32 + j * 8 + 4];
            uint4 o;
            o.x = pkbf(a.x, a.y); o.y = pkbf(a.z, a.w);
            o.z = pkbf(b.x, b.y); o.w = pkbf(b.z, b.w);
            *(uint4*)((char*)Sb + (dbase + j * 8) * 2) = o;
        }
        __syncthreads();
    }
}

// =====================================================================
// attn_mma: unchanged (round-11, passing).
// =====================================================================
#define SROW  1028
#define AS_MB 65792
#define AS_QH 69888
#define AS_QL 72192
#define AS_KB 74496
#define KLO   18432
#define ATTN_SMEM 111360

__global__ __launch_bounds__(256, 2) void attn_mma(
    const __nv_bfloat16* __restrict__ Qhh, const __nv_bfloat16* __restrict__ Qhl,
    const __nv_bfloat16* __restrict__ Khh, const __nv_bfloat16* __restrict__ Khl,
    const __nv_bfloat16* __restrict__ Vhh, const __nv_bfloat16* __restrict__ Vhl,
    const __nv_bfloat16* __restrict__ Sb,
    const int* __restrict__ mask, float* __restrict__ attn,
    __nv_bfloat16* __restrict__ Ch, __nv_bfloat16* __restrict__ Cl)
{
    extern __shared__ __align__(128) char smem[];
    u32 sbp = smem_u32(smem);
    float* S  = (float*)smem;
    float* mb = (float*)(smem + AS_MB);
    int tid = threadIdx.x, wid = tid >> 5, lane = tid & 31;
    int bh  = blockIdx.x;
    int q0  = blockIdx.y * 16;
    int b = bh >> 3, h = bh & 7;
    const float scale = 0.125f;

    const __nv_bfloat16* KhB = Khh + (size_t)bh * NKV * DHD;
    const __nv_bfloat16* KlB = Khl + (size_t)bh * NKV * DHD;
    const __nv_bfloat16* VhB = Vhh + (size_t)bh * NKV * DHD;
    const __nv_bfloat16* VlB = Vhl + (size_t)bh * NKV * DHD;

    if (tid < 128) {
        int row = tid >> 3, c4 = tid & 7;
        u32 off = (u32)(row * 144 + c4 * 16);
        size_t e = ((size_t)bh * NQ + q0 + row) * DHD + c4 * 8;
        *(uint4*)(smem + AS_QH + off) = *(const uint4*)((const char*)Qhh + e * 2);
        *(uint4*)(smem + AS_QL + off) = *(const uint4*)((const char*)Qhl + e * 2);
    }
    for (int k = tid; k < NKV; k += 256)
        mb[k] = mask[b * NKV + k] ? 0.f : -1e30f;
    __syncthreads();

    u32 qh[4][4], ql[4][4];
#pragma unroll
    for (int ds = 0; ds < 4; ds++) {
        u32 ra = (u32)((lane & 15) * 72 + ds * 16 + ((lane >> 4) << 3)) * 2;
        ldm_x4(qh[ds], sbp + AS_QH + ra);
        ldm_x4(ql[ds], sbp + AS_QL + ra);
    }

    int prow = tid >> 3, pc4 = tid & 7;
    u32 poff0 = (u32)(prow * 144 + pc4 * 16);
    size_t psrc0 = (size_t)prow * 64 + pc4 * 8;

#define ISSUE_CHUNK(HIptr, LOptr, cix) do {                                        \
        u32 dh_ = sbp + AS_KB;                                                     \
        u32 dl_ = dh_ + KLO;                                                       \
        const char* sh_ = (const char*)((HIptr) + (size_t)(cix) * 128 * 64);       \
        const char* sl_ = (const char*)((LOptr) + (size_t)(cix) * 128 * 64);       \
        _Pragma("unroll")                                                          \
        for (int r_ = 0; r_ < 4; r_++) {                                           \
            u32 o_ = poff0 + (u32)r_ * 32 * 144;                                   \
            size_t s_ = (psrc0 + (size_t)r_ * 32 * 64) * 2;                        \
            CP_ASYNC16(dh_ + o_, sh_ + s_);                                        \
            CP_ASYNC16(dl_ + o_, sl_ + s_);                                        \
        }                                                                          \
        CP_COMMIT();                                                               \
    } while (0)

    // ---- Phase 1: QK^T + Sb + mask ----
    for (int c = 0; c < 8; c++) {
        ISSUE_CHUNK(KhB, KlB, c);
        CP_WAIT0();
        __syncthreads();
        u32 bufH = sbp + AS_KB, bufL = bufH + KLO;

        float acc[2][4];
#pragma unroll
        for (int j = 0; j < 2; j++)
#pragma unroll
            for (int t = 0; t < 4; t++) acc[j][t] = 0.f;

#pragma unroll
        for (int ds = 0; ds < 4; ds++) {
            u32 rb = (u32)((wid * 16 + (lane & 15)) * 72 + ds * 16 + ((lane >> 4) << 3)) * 2;
            u32 kh4[4], kl4[4];
            ldm_x4(kh4, bufH + rb);
            ldm_x4(kl4, bufL + rb);
            mma_bf16(acc[0], qh[ds], kh4[0], kh4[2]);
            mma_bf16(acc[0], qh[ds], kl4[0], kl4[2]);
            mma_bf16(acc[0], ql[ds], kh4[0], kh4[2]);
            mma_bf16(acc[1], qh[ds], kh4[1], kh4[3]);
            mma_bf16(acc[1], qh[ds], kl4[1], kl4[3]);
            mma_bf16(acc[1], ql[ds], kh4[1], kh4[3]);
        }
        int qq = lane >> 2;
#pragma unroll
        for (int j = 0; j < 2; j++) {
            int k = c * 128 + wid * 16 + j * 8 + (lane & 3) * 2;
            u32 u0 = *(const u32*)((const char*)Sb + (((size_t)(q0 + qq) * BHN + bh) * NKV + k) * 2);
            u32 u1 = *(const u32*)((const char*)Sb + (((size_t)(q0 + qq + 8) * BHN + bh) * NKV + k) * 2);
            float2 b0 = __bfloat1622float2(*(__nv_bfloat162*)&u0);
            float2 b1 = __bfloat1622float2(*(__nv_bfloat162*)&u1);
            float2 mm = *(const float2*)&mb[k];
            *(float2*)&S[qq * SROW + k] = make_float2(
                (acc[j][0] + b0.x) * scale + mm.x,
                (acc[j][1] + b0.y) * scale + mm.y);
            *(float2*)&S[(qq + 8) * SROW + k] = make_float2(
                (acc[j][2] + b1.x) * scale + mm.x,
                (acc[j][3] + b1.y) * scale + mm.y);
        }
        __syncthreads();
    }

    // ---- Phase 2: softmax + attn store ----
    for (int r = 0; r < 2; r++) {
        float* row = S + (wid * 2 + r) * SROW;
        float m = -3.4e38f;
        for (int k = lane; k < NKV; k += 32) m = fmaxf(m, row[k]);
#pragma unroll
        for (int o = 16; o; o >>= 1) m = fmaxf(m, __shfl_xor_sync(0xffffffffu, m, o));
        float s = 0.f;
        for (int k = lane; k < NKV; k += 32) {
            float e = __expf(row[k] - m);
            row[k] = e; s += e;
        }
#pragma unroll
        for (int o = 16; o; o >>= 1) s += __shfl_xor_sync(0xffffffffu, s, o);
        float inv = 1.f / s;
        __syncwarp();
        float* arow = attn + ((size_t)bh * NQ + q0 + wid * 2 + r) * NKV;
        for (int k = lane * 4; k < NKV; k += 128) {
            float4 v = *(float4*)&row[k];
            v.x *= inv; v.y *= inv; v.z *= inv; v.w *= inv;
            *(float4*)&row[k] = v;
            *(float4*)&arow[k] = v;
        }
        __syncwarp();
    }
    __syncthreads();

    // ---- Phase 3: ctx = P @ V ----
    float acc[8][4];
#pragma unroll
    for (int j = 0; j < 8; j++)
#pragma unroll
        for (int t = 0; t < 4; t++) acc[j][t] = 0.f;

    for (int c = 0; c < 8; c++) {
        ISSUE_CHUNK(VhB, VlB, c);
        CP_WAIT0();
        __syncthreads();
        u32 bufH = sbp + AS_KB, bufL = bufH + KLO;
        int kbase = c * 128 + wid * 16;

        u32 ph[4], pl[4];
        {
            int r0 = lane >> 2;
            const float* Sr0 = S + r0 * SROW;
            const float* Sr1 = S + (r0 + 8) * SROW;
            int cc = kbase + (lane & 3) * 2;
            split2(*(const float2*)(Sr0 + cc),     ph[0], pl[0]);
            split2(*(const float2*)(Sr1 + cc),     ph[1], pl[1]);
            split2(*(const float2*)(Sr0 + cc + 8), ph[2], pl[2]);
            split2(*(const float2*)(Sr1 + cc + 8), ph[3], pl[3]);
        }
#pragma unroll
        for (int dn = 0; dn < 4; dn++) {
            u32 rv = (u32)((wid * 16 + (lane & 15)) * 72 + dn * 16 + ((lane >> 4) << 3)) * 2;
            u32 vh4[4], vl4[4];
            ldm_x4t(vh4, bufH + rv);
            ldm_x4t(vl4, bufL + rv);
            mma_bf16(acc[dn*2],   ph, vh4[0], vh4[1]);
            mma_bf16(acc[dn*2],   ph, vl4[0], vl4[1]);
            mma_bf16(acc[dn*2],   pl, vh4[0], vh4[1]);
            mma_bf16(acc[dn*2+1], ph, vh4[2], vh4[3]);
            mma_bf16(acc[dn*2+1], ph, vl4[2], vl4[3]);
            mma_bf16(acc[dn*2+1], pl, vh4[2], vh4[3]);
        }
        __syncthreads();
    }

    float* slab = (float*)(smem + AS_KB);
    {
        int qq = lane >> 2;
#pragma unroll
        for (int j = 0; j < 8; j++) {
            int d = j * 8 + (lane & 3) * 2;
            *(float2*)&slab[(wid * 16 + qq) * 68 + d]     = make_float2(acc[j][0], acc[j][1]);
            *(float2*)&slab[(wid * 16 + qq + 8) * 68 + d] = make_float2(acc[j][2], acc[j][3]);
        }
    }
    __syncthreads();

    {
        int qq = tid >> 4, db = (tid & 15) * 4;
        float s[4] = {0.f, 0.f, 0.f, 0.f};
#pragma unroll
        for (int w = 0; w < 8; w++) {
            const float* p = &slab[(w * 16 + qq) * 68 + db];
#pragma unroll
            for (int t = 0; t < 4; t++) s[t] += p[t];
        }
        size_t e = ((size_t)b * NQ + q0 + qq) * DM + h * DHD + db;
        u32 h0, l0, h1, l1;
        split2(make_float2(s[0], s[1]), h0, l0);
        split2(make_float2(s[2], s[3]), h1, l1);
        *(u32*)((char*)Ch + e * 2)     = h0;
        *(u32*)((char*)Ch + e * 2 + 4) = h1;
        *(u32*)((char*)Cl + e * 2)     = l0;
        *(u32*)((char*)Cl + e * 2 + 4) = l1;
    }
}

// =====================================================================
// launcher
// =====================================================================
extern "C" void kernel_launch(void* const* d_in, const int* in_sizes, int n_in,
                              void* d_out, int out_size)
{
    const float* q    = (const float*)d_in[0];
    const float* kv   = (const float*)d_in[1];
    const int*   mask = (const int*)  d_in[2];
    const float* Wq   = (const float*)d_in[3];
    const float* bq   = (const float*)d_in[4];
    const float* Wk   = (const float*)d_in[5];
    const float* bk   = (const float*)d_in[6];
    const float* Wv   = (const float*)d_in[7];
    const float* bv   = (const float*)d_in[8];
    const float* Wo   = (const float*)d_in[9];
    const float* bo   = (const float*)d_in[10];
    const float* R    = (const float*)d_in[11];

    float* out = (float*)d_out;
    const size_t out_elems  = (size_t)BB*NQ*DM;
    const size_t attn_elems = (size_t)BHN*NQ*NKV;

    __nv_bfloat16 *Qhh, *Qhl, *Khh, *Khl, *Vhh, *Vhl, *Sb;
    __nv_bfloat16 *qh, *ql2, *kvh, *kvl, *ch, *cl, *Wh, *Wl;
    float *attn_fb;
    cudaGetSymbolAddress((void**)&Qhh, g_Qhh);
    cudaGetSymbolAddress((void**)&Qhl, g_Qhl);
    cudaGetSymbolAddress((void**)&Khh, g_Khh);
    cudaGetSymbolAddress((void**)&Khl, g_Khl);
    cudaGetSymbolAddress((void**)&Vhh, g_Vhh);
    cudaGetSymbolAddress((void**)&Vhl, g_Vhl);
    cudaGetSymbolAddress((void**)&Sb,  g_Sb);
    cudaGetSymbolAddress((void**)&qh,  g_qh);
    cudaGetSymbolAddress((void**)&ql2, g_ql);
    cudaGetSymbolAddress((void**)&kvh, g_kvh);
    cudaGetSymbolAddress((void**)&kvl, g_kvl);
    cudaGetSymbolAddress((void**)&ch,  g_ch);
    cudaGetSymbolAddress((void**)&cl,  g_cl);
    cudaGetSymbolAddress((void**)&Wh,  g_Wh);
    cudaGetSymbolAddress((void**)&Wl,  g_Wl);
    cudaGetSymbolAddress((void**)&attn_fb, g_attn_fallback);

    float* attn = ((size_t)out_size >= out_elems + attn_elems)
                ? (out + out_elems) : attn_fb;

    cudaFuncSetAttribute(proj_bf,  cudaFuncAttributeMaxDynamicSharedMemorySize, PROJB_SMEM);
    cudaFuncSetAttribute(bias_mma, cudaFuncAttributeMaxDynamicSharedMemorySize, BIAS_SMEM);
    cudaFuncSetAttribute(attn_mma, cudaFuncAttributeMaxDynamicSharedMemorySize, ATTN_SMEM);

    const size_t WSZ = (size_t)DM * DM;
    cvt<<<4096, 256>>>(q,  qh,  ql2, (int)(out_elems / 4));
    cvt<<<4096, 256>>>(kv, kvh, kvl, (int)(out_elems / 4));
    cvt<<<256, 256>>>(Wq, Wh + 0*WSZ, Wl + 0*WSZ, (int)(WSZ / 4));
    cvt<<<256, 256>>>(Wk, Wh + 1*WSZ, Wl + 1*WSZ, (int)(WSZ / 4));
    cvt<<<256, 256>>>(Wv, Wh + 2*WSZ, Wl + 2*WSZ, (int)(WSZ / 4));
    cvt<<<256, 256>>>(Wo, Wh + 3*WSZ, Wl + 3*WSZ, (int)(WSZ / 4));

    dim3 gProj(4, 64);
    proj_bf<<<gProj, 256, PROJB_SMEM>>>(qh,  ql2, Wh + 0*WSZ, Wl + 0*WSZ, bq, nullptr, Qhh, Qhl, 1);
    proj_bf<<<gProj, 256, PROJB_SMEM>>>(kvh, kvl, Wh + 1*WSZ, Wl + 1*WSZ, bk, nullptr, Khh, Khl, 1);
    proj_bf<<<gProj, 256, PROJB_SMEM>>>(kvh, kvl, Wh + 2*WSZ, Wl + 2*WSZ, bv, nullptr, Vhh, Vhl, 1);

    bias_mma<<<dim3(2, 1024), 256, BIAS_SMEM>>>(Qhh, Qhl, R, Sb);

    attn_mma<<<dim3(64, 64), 256, ATTN_SMEM>>>(Qhh, Qhl, Khh, Khl, Vhh, Vhl,
                                               Sb, mask, attn, ch, cl);

    proj_bf<<<gProj, 256, PROJB_SMEM>>>(ch, cl, Wh + 3*WSZ, Wl + 3*WSZ, bo, out, nullptr, nullptr, 0);
}

// round 14
// speedup vs baseline: 1.0126x; 1.0010x over previous
#include <cuda_runtime.h>
#include <cuda_bf16.h>
#include <cstdint>
#include <cstddef>

#define BB    8
#define HH    8
#define NQ    1024
#define NKV   1024
#define DHD   64
#define DM    512
#define BHN   (BB*HH)

typedef unsigned long long ull;
typedef uint32_t u32;

__device__ __forceinline__ u32 smem_u32(const void* p) {
    u32 a;
    asm("{ .reg .u64 t; cvta.to.shared.u64 t, %1; cvt.u32.u64 %0, t; }" : "=r"(a) : "l"(p));
    return a;
}
__device__ __forceinline__ void ldm_x4(u32* r, u32 a) {
    asm volatile("ldmatrix.sync.aligned.m8n8.x4.shared.b16 {%0,%1,%2,%3}, [%4];"
        : "=r"(r[0]),"=r"(r[1]),"=r"(r[2]),"=r"(r[3]) : "r"(a));
}
__device__ __forceinline__ void ldm_x4t(u32* r, u32 a) {
    asm volatile("ldmatrix.sync.aligned.m8n8.x4.trans.shared.b16 {%0,%1,%2,%3}, [%4];"
        : "=r"(r[0]),"=r"(r[1]),"=r"(r[2]),"=r"(r[3]) : "r"(a));
}
__device__ __forceinline__ void mma_bf16(float* c, const u32* a, u32 b0, u32 b1) {
    asm volatile("mma.sync.aligned.m16n8k16.row.col.f32.bf16.bf16.f32 "
        "{%0,%1,%2,%3}, {%4,%5,%6,%7}, {%8,%9}, {%0,%1,%2,%3};"
        : "+f"(c[0]),"+f"(c[1]),"+f"(c[2]),"+f"(c[3])
        : "r"(a[0]),"r"(a[1]),"r"(a[2]),"r"(a[3]), "r"(b0),"r"(b1));
}
__device__ __forceinline__ void split4(float4 v, ull& hi8, ull& lo8) {
    __nv_bfloat162 h01 = __floats2bfloat162_rn(v.x, v.y);
    __nv_bfloat162 h23 = __floats2bfloat162_rn(v.z, v.w);
    float2 f01 = __bfloat1622float2(h01);
    float2 f23 = __bfloat1622float2(h23);
    __nv_bfloat162 l01 = __floats2bfloat162_rn(v.x - f01.x, v.y - f01.y);
    __nv_bfloat162 l23 = __floats2bfloat162_rn(v.z - f23.x, v.w - f23.y);
    u32 uh0 = *(u32*)&h01, uh1 = *(u32*)&h23;
    u32 ul0 = *(u32*)&l01, ul1 = *(u32*)&l23;
    hi8 = (ull)uh0 | ((ull)uh1 << 32);
    lo8 = (ull)ul0 | ((ull)ul1 << 32);
}
__device__ __forceinline__ void split2(float2 v, u32& h, u32& l) {
    __nv_bfloat162 hb = __floats2bfloat162_rn(v.x, v.y);
    float2 hf = __bfloat1622float2(hb);
    __nv_bfloat162 lb = __floats2bfloat162_rn(v.x - hf.x, v.y - hf.y);
    h = *(u32*)&hb; l = *(u32*)&lb;
}
__device__ __forceinline__ u32 pkbf(float x, float y) {
    __nv_bfloat162 t = __floats2bfloat162_rn(x, y);
    return *(u32*)&t;
}

#define CP_ASYNC16(dst, src) \
    asm volatile("cp.async.ca.shared.global [%0], [%1], 16;" :: "r"(dst), "l"(src) : "memory")
#define CP_COMMIT() asm volatile("cp.async.commit_group;" ::: "memory")
#define CP_WAIT0()  asm volatile("cp.async.wait_group 0;" ::: "memory")
#define CP_WAIT1()  asm volatile("cp.async.wait_group 1;" ::: "memory")

// ---------------- device scratch ----------------
__device__ __nv_bfloat16 g_Qhh[(size_t)BHN*NQ*DHD];
__device__ __nv_bfloat16 g_Qhl[(size_t)BHN*NQ*DHD];
__device__ __nv_bfloat16 g_Khh[(size_t)BHN*NKV*DHD];
__device__ __nv_bfloat16 g_Khl[(size_t)BHN*NKV*DHD];
__device__ __nv_bfloat16 g_Vhh[(size_t)BHN*NKV*DHD];
__device__ __nv_bfloat16 g_Vhl[(size_t)BHN*NKV*DHD];
__device__ __nv_bfloat16 g_Sb[(size_t)NQ*BHN*NKV];
__device__ __nv_bfloat16 g_qh[(size_t)BB*NQ*DM],  g_ql[(size_t)BB*NQ*DM];
__device__ __nv_bfloat16 g_kvh[(size_t)BB*NKV*DM], g_kvl[(size_t)BB*NKV*DM];
__device__ __nv_bfloat16 g_ch[(size_t)BB*NQ*DM],  g_cl[(size_t)BB*NQ*DM];
__device__ __nv_bfloat16 g_Wh[(size_t)4*DM*DM],   g_Wl[(size_t)4*DM*DM];
__device__ float g_attn_fallback[(size_t)BHN*NQ*NKV];

// =====================================================================
// cvt: fp32 -> bf16 hi/lo split
// =====================================================================
__global__ void cvt(const float* __restrict__ x,
                    __nv_bfloat16* __restrict__ h, __nv_bfloat16* __restrict__ l, int n4)
{
    int i = blockIdx.x * blockDim.x + threadIdx.x;
    if (i < n4) {
        float4 v = ((const float4*)x)[i];
        ull h8, l8; split4(v, h8, l8);
        ((ull*)h)[i] = h8;
        ((ull*)l)[i] = l8;
    }
}

// =====================================================================
// proj_bf: round-13 version (K-chunks of 32, occ 2) — unchanged.
// =====================================================================
#define PB_AH 0
#define PB_AL 10240
#define PB_WH 20480
#define PB_WL 29184
#define PB_STAGE 37888
#define PROJB_SMEM (2*PB_STAGE)

__global__ __launch_bounds__(256, 2) void proj_bf(
    const __nv_bfloat16* __restrict__ Ah, const __nv_bfloat16* __restrict__ Al,
    const __nv_bfloat16* __restrict__ Wh, const __nv_bfloat16* __restrict__ Wl,
    const float* __restrict__ bias, float* __restrict__ C,
    __nv_bfloat16* __restrict__ Ohi, __nv_bfloat16* __restrict__ Olo,
    int permute)
{
    extern __shared__ __align__(128) char smem[];
    u32 sb = smem_u32(smem);
    int tid = threadIdx.x, wid = tid >> 5, lane = tid & 31;
    int m0 = blockIdx.y * 128, n0 = blockIdx.x * 128;
    int wm = wid & 3, wn = wid >> 2;

    int arow = tid >> 2, ac = tid & 3;
    int wrow = tid >> 4, wc16 = tid & 15;

#define PB_ISSUE(kb, buf) do {                                                       \
        u32 base_ = sb + (buf) * PB_STAGE;                                           \
        _Pragma("unroll")                                                            \
        for (int r_ = 0; r_ < 2; r_++) {                                             \
            int row_ = arow + r_ * 64;                                               \
            u32 d_ = base_ + (u32)(row_ * 80 + ac * 16);                             \
            size_t s_ = ((size_t)(m0 + row_) * 512 + (kb) * 32 + ac * 8) * 2;        \
            CP_ASYNC16(d_ + PB_AH, (const char*)Ah + s_);                            \
            CP_ASYNC16(d_ + PB_AL, (const char*)Al + s_);                            \
        }                                                                            \
        _Pragma("unroll")                                                            \
        for (int r_ = 0; r_ < 2; r_++) {                                             \
            int row_ = wrow + r_ * 16;                                               \
            u32 d_ = base_ + (u32)(row_ * 272 + wc16 * 16);                          \
            size_t s_ = ((size_t)((kb) * 32 + row_) * 512 + n0 + wc16 * 8) * 2;      \
            CP_ASYNC16(d_ + PB_WH, (const char*)Wh + s_);                            \
            CP_ASYNC16(d_ + PB_WL, (const char*)Wl + s_);                            \
        }                                                                            \
        CP_COMMIT();                                                                 \
    } while (0)

    float acc[2][8][4];
#pragma unroll
    for (int m = 0; m < 2; m++)
#pragma unroll
        for (int j = 0; j < 8; j++)
#pragma unroll
            for (int t = 0; t < 4; t++) acc[m][j][t] = 0.f;

    PB_ISSUE(0, 0);
    for (int kb = 0; kb < 16; kb++) {
        if (kb < 15) { PB_ISSUE(kb + 1, (kb + 1) & 1); CP_WAIT1(); }
        else CP_WAIT0();
        __syncthreads();
        u32 base = sb + (kb & 1) * PB_STAGE;

#pragma unroll
        for (int ks = 0; ks < 2; ks++) {
            u32 ah[2][4], al[2][4];
#pragma unroll
            for (int f = 0; f < 2; f++) {
                u32 ra = base + PB_AH
                       + (u32)((wm * 32 + f * 16 + (lane & 15)) * 80 + (ks * 16 + ((lane >> 4) << 3)) * 2);
                ldm_x4(ah[f], ra);
                ldm_x4(al[f], ra + (PB_AL - PB_AH));
            }
#pragma unroll
            for (int nf = 0; nf < 4; nf++) {
                u32 rb = base + PB_WH
                       + (u32)((ks * 16 + (lane & 15)) * 272 + (wn * 64 + nf * 16 + ((lane >> 4) << 3)) * 2);
                u32 bh4[4], bl4[4];
                ldm_x4t(bh4, rb);
                ldm_x4t(bl4, rb + (PB_WL - PB_WH));
#pragma unroll
                for (int m = 0; m < 2; m++) {
                    mma_bf16(acc[m][nf*2],   ah[m], bh4[0], bh4[1]);
                    mma_bf16(acc[m][nf*2],   ah[m], bl4[0], bl4[1]);
                    mma_bf16(acc[m][nf*2],   al[m], bh4[0], bh4[1]);
                    mma_bf16(acc[m][nf*2+1], ah[m], bh4[2], bh4[3]);
                    mma_bf16(acc[m][nf*2+1], ah[m], bl4[2], bl4[3]);
                    mma_bf16(acc[m][nf*2+1], al[m], bh4[2], bh4[3]);
                }
            }
        }
        __syncthreads();
    }

    int r0 = m0 + wm * 32 + (lane >> 2);
    int cb = n0 + wn * 64 + (lane & 3) * 2;
#pragma unroll
    for (int m = 0; m < 2; m++) {
#pragma unroll
        for (int j = 0; j < 8; j++) {
            int col = cb + j * 8;
            float2 bv = *(const float2*)&bias[col];
            int rowA = r0 + m * 16, rowB = rowA + 8;
            float2 vA = make_float2(acc[m][j][0] + bv.x, acc[m][j][1] + bv.y);
            float2 vB = make_float2(acc[m][j][2] + bv.x, acc[m][j][3] + bv.y);
            if (permute) {
                int h = col >> 6, dd = col & 63;
                size_t eA = ((size_t)((rowA >> 10) * HH + h) * NQ + (rowA & 1023)) * 64 + dd;
                size_t eB = ((size_t)((rowB >> 10) * HH + h) * NQ + (rowB & 1023)) * 64 + dd;
                u32 hA, lA, hB, lB;
                split2(vA, hA, lA); split2(vB, hB, lB);
                *(u32*)((char*)Ohi + eA * 2) = hA;
                *(u32*)((char*)Olo + eA * 2) = lA;
                *(u32*)((char*)Ohi + eB * 2) = hB;
                *(u32*)((char*)Olo + eB * 2) = lB;
            } else {
                *(float2*)(C + (size_t)rowA * 512 + col) = vA;
                *(float2*)(C + (size_t)rowB * 512 + col) = vB;
            }
        }
    }
}

// =====================================================================
// bias_mma: round-11 version — unchanged.
// =====================================================================
#define BZ_RH 0
#define BZ_QH 36864
#define BZ_QL 46080
#define BIAS_SMEM 55296

__global__ __launch_bounds__(256) void bias_mma(
    const __nv_bfloat16* __restrict__ Qhh, const __nv_bfloat16* __restrict__ Qhl,
    const float* __restrict__ R, __nv_bfloat16* __restrict__ Sb)
{
    extern __shared__ __align__(128) char smem[];
    u32 sb = smem_u32(smem);
    int tid = threadIdx.x, wid = tid >> 5, lane = tid & 31;
    int wm = wid & 3, wn = wid >> 2;
    int q = blockIdx.y, kc = blockIdx.x;

#pragma unroll
    for (int r = 0; r < 2; r++) {
        int idx = tid + r * 256;
        int row = idx >> 3, c4 = idx & 7;
        u32 off = (u32)(row * 144 + c4 * 16);
        size_t e = ((size_t)row * NQ + q) * DHD + c4 * 8;
        *(uint4*)(smem + BZ_QH + off) = *(const uint4*)((const char*)Qhh + e * 2);
        *(uint4*)(smem + BZ_QL + off) = *(const uint4*)((const char*)Qhl + e * 2);
    }
    __syncthreads();

    u32 qh4[4][2][4], ql4[4][2][4];
#pragma unroll
    for (int ks = 0; ks < 4; ks++)
#pragma unroll
        for (int g = 0; g < 2; g++) {
            u32 rb = (u32)((wn * 32 + g * 16 + (lane & 7) + ((lane >> 4) << 3)) * 72
                           + ks * 16 + (((lane >> 3) & 1) << 3)) * 2;
            ldm_x4(qh4[ks][g], sb + BZ_QH + rb);
            ldm_x4(ql4[ks][g], sb + BZ_QL + rb);
        }

    for (int kt = 0; kt < 4; kt++) {
        int k0 = (kc * 4 + kt) * 128;
#pragma unroll
        for (int r = 0; r < 8; r++) {
            int idx = tid + r * 256;
            int row = idx >> 4, col = (idx & 15) << 2;
            float4 v = *(const float4*)(R + ((size_t)q * NKV + k0 + row) * DHD + col);
            u32 p0 = pkbf(v.x, v.y), p1 = pkbf(v.z, v.w);
            *(ull*)(smem + BZ_RH + (row * 72 + col) * 2) = (ull)p0 | ((ull)p1 << 32);
        }
        __syncthreads();

        float acc[2][4][4];
#pragma unroll
        for (int m = 0; m < 2; m++)
#pragma unroll
            for (int j = 0; j < 4; j++)
#pragma unroll
                for (int t = 0; t < 4; t++) acc[m][j][t] = 0.f;

#pragma unroll
        for (int ks = 0; ks < 4; ks++) {
            u32 ah[2][4];
#pragma unroll
            for (int f = 0; f < 2; f++) {
                u32 ra = (u32)((wm * 32 + f * 16 + (lane & 15)) * 72 + ks * 16 + ((lane >> 4) << 3)) * 2;
                ldm_x4(ah[f], sb + BZ_RH + ra);
            }
#pragma unroll
            for (int g = 0; g < 2; g++)
#pragma unroll
                for (int m = 0; m < 2; m++) {
                    mma_bf16(acc[m][g*2],   ah[m], qh4[ks][g][0], qh4[ks][g][1]);
                    mma_bf16(acc[m][g*2],   ah[m], ql4[ks][g][0], ql4[ks][g][1]);
                    mma_bf16(acc[m][g*2+1], ah[m], qh4[ks][g][2], qh4[ks][g][3]);
                    mma_bf16(acc[m][g*2+1], ah[m], ql4[ks][g][2], ql4[ks][g][3]);
                }
        }
        __syncthreads();

        float* T = (float*)smem;
#pragma unroll
        for (int m = 0; m < 2; m++) {
            int krow = wm * 32 + m * 16 + (lane >> 2);
#pragma unroll
            for (int j = 0; j < 4; j++) {
                int bhc = wn * 32 + j * 8 + (lane & 3) * 2;
                T[bhc * 132 + krow]           = acc[m][j][0];
                T[(bhc + 1) * 132 + krow]     = acc[m][j][1];
                T[bhc * 132 + krow + 8]       = acc[m][j][2];
                T[(bhc + 1) * 132 + krow + 8] = acc[m][j][3];
            }
        }
        __syncthreads();

        int bh2 = tid >> 2, part = tid & 3;
        size_t dbase = ((size_t)q * BHN + bh2) * NKV + k0 + part * 32;
#pragma unroll
        for (int j = 0; j < 4; j++) {
            float4 a = *(float4*)&T[bh2 * 132 + part * 32 + j * 8];
            float4 b = *(float4*)&T[bh2 * 132 + part * 32 + j * 8 + 4];
            uint4 o;
            o.x = pkbf(a.x, a.y); o.y = pkbf(a.z, a.w);
            o.z = pkbf(b.x, b.y); o.w = pkbf(b.z, b.w);
            *(uint4*)((char*)Sb + (dbase + j * 8) * 2) = o;
        }
        __syncthreads();
    }
}

// =====================================================================
// attn_mma v3: q-tile 32, 512 threads (16 warps), chunks of 256 k.
// smem: S fp32 32x1028 (131584) | mb 4096 | QH 4608 | QL 4608 |
//       KV hi 36864 + lo 36864  -> total 218624. occ 1.
// Slab reduce reuses S region after P is consumed.
// =====================================================================
#define SROW  1028
#define AS_MB 131584
#define AS_QH 135680
#define AS_QL 140288
#define AS_KB 144896
#define KLO   36864
#define ATTN_SMEM 218624

__global__ __launch_bounds__(512, 1) void attn_mma(
    const __nv_bfloat16* __restrict__ Qhh, const __nv_bfloat16* __restrict__ Qhl,
    const __nv_bfloat16* __restrict__ Khh, const __nv_bfloat16* __restrict__ Khl,
    const __nv_bfloat16* __restrict__ Vhh, const __nv_bfloat16* __restrict__ Vhl,
    const __nv_bfloat16* __restrict__ Sb,
    const int* __restrict__ mask, float* __restrict__ attn,
    __nv_bfloat16* __restrict__ Ch, __nv_bfloat16* __restrict__ Cl)
{
    extern __shared__ __align__(128) char smem[];
    u32 sbp = smem_u32(smem);
    float* S  = (float*)smem;
    float* mb = (float*)(smem + AS_MB);
    int tid = threadIdx.x, wid = tid >> 5, lane = tid & 31;
    int bh  = blockIdx.x;
    int q0  = blockIdx.y * 32;
    int b = bh >> 3, h = bh & 7;
    const float scale = 0.125f;

    const __nv_bfloat16* KhB = Khh + (size_t)bh * NKV * DHD;
    const __nv_bfloat16* KlB = Khl + (size_t)bh * NKV * DHD;
    const __nv_bfloat16* VhB = Vhh + (size_t)bh * NKV * DHD;
    const __nv_bfloat16* VlB = Vhl + (size_t)bh * NKV * DHD;

    if (tid < 256) {
        int row = tid >> 3, c4 = tid & 7;
        u32 off = (u32)(row * 144 + c4 * 16);
        size_t e = ((size_t)bh * NQ + q0 + row) * DHD + c4 * 8;
        *(uint4*)(smem + AS_QH + off) = *(const uint4*)((const char*)Qhh + e * 2);
        *(uint4*)(smem + AS_QL + off) = *(const uint4*)((const char*)Qhl + e * 2);
    }
    for (int k = tid; k < NKV; k += 512)
        mb[k] = mask[b * NKV + k] ? 0.f : -1e30f;
    __syncthreads();

    // hoist Q fragments: 4 d-steps x 2 m
    u32 qh[4][2][4], ql[4][2][4];
#pragma unroll
    for (int ds = 0; ds < 4; ds++)
#pragma unroll
        for (int m = 0; m < 2; m++) {
            u32 ra = (u32)((m * 16 + (lane & 15)) * 144 + (ds * 16 + ((lane >> 4) << 3)) * 2);
            ldm_x4(qh[ds][m], sbp + AS_QH + ra);
            ldm_x4(ql[ds][m], sbp + AS_QL + ra);
        }

    // chunk copy: 256 rows x 8 uint4 per array, 512 threads, 4 iters
    int prow = tid >> 3, pc4 = tid & 7;
    u32 poff0 = (u32)(prow * 144 + pc4 * 16);
    size_t psrc0 = (size_t)prow * 64 + pc4 * 8;

#define ISSUE_CHUNK(HIptr, LOptr, cix) do {                                        \
        u32 dh_ = sbp + AS_KB;                                                     \
        u32 dl_ = dh_ + KLO;                                                       \
        const char* sh_ = (const char*)((HIptr) + (size_t)(cix) * 256 * 64);       \
        const char* sl_ = (const char*)((LOptr) + (size_t)(cix) * 256 * 64);       \
        _Pragma("unroll")                                                          \
        for (int r_ = 0; r_ < 4; r_++) {                                           \
            u32 o_ = poff0 + (u32)r_ * 64 * 144;                                   \
            size_t s_ = (psrc0 + (size_t)r_ * 64 * 64) * 2;                        \
            CP_ASYNC16(dh_ + o_, sh_ + s_);                                        \
            CP_ASYNC16(dl_ + o_, sl_ + s_);                                        \
        }                                                                          \
        CP_COMMIT();                                                               \
    } while (0)

    // ---- Phase 1: QK^T + Sb + mask, 4 chunks of 256 k ----
    for (int c = 0; c < 4; c++) {
        ISSUE_CHUNK(KhB, KlB, c);
        CP_WAIT0();
        __syncthreads();
        u32 bufH = sbp + AS_KB, bufL = bufH + KLO;

        float acc[2][2][4];
#pragma unroll
        for (int m = 0; m < 2; m++)
#pragma unroll
            for (int j = 0; j < 2; j++)
#pragma unroll
                for (int t = 0; t < 4; t++) acc[m][j][t] = 0.f;

#pragma unroll
        for (int ds = 0; ds < 4; ds++) {
            u32 rb = (u32)((wid * 16 + (lane & 15)) * 144 + (ds * 16 + ((lane >> 4) << 3)) * 2);
            u32 kh4[4], kl4[4];
            ldm_x4(kh4, bufH + rb);
            ldm_x4(kl4, bufL + rb);
#pragma unroll
            for (int m = 0; m < 2; m++) {
                mma_bf16(acc[m][0], qh[ds][m], kh4[0], kh4[2]);
                mma_bf16(acc[m][0], qh[ds][m], kl4[0], kl4[2]);
                mma_bf16(acc[m][0], ql[ds][m], kh4[0], kh4[2]);
                mma_bf16(acc[m][1], qh[ds][m], kh4[1], kh4[3]);
                mma_bf16(acc[m][1], qh[ds][m], kl4[1], kl4[3]);
                mma_bf16(acc[m][1], ql[ds][m], kh4[1], kh4[3]);
            }
        }
        int qq = lane >> 2;
#pragma unroll
        for (int m = 0; m < 2; m++) {
            int r0 = m * 16 + qq, r1 = r0 + 8;
#pragma unroll
            for (int j = 0; j < 2; j++) {
                int k = c * 256 + wid * 16 + j * 8 + (lane & 3) * 2;
                u32 u0 = *(const u32*)((const char*)Sb + (((size_t)(q0 + r0) * BHN + bh) * NKV + k) * 2);
                u32 u1 = *(const u32*)((const char*)Sb + (((size_t)(q0 + r1) * BHN + bh) * NKV + k) * 2);
                float2 b0 = __bfloat1622float2(*(__nv_bfloat162*)&u0);
                float2 b1 = __bfloat1622float2(*(__nv_bfloat162*)&u1);
                float2 mm = *(const float2*)&mb[k];
                *(float2*)&S[r0 * SROW + k] = make_float2(
                    (acc[m][j][0] + b0.x) * scale + mm.x,
                    (acc[m][j][1] + b0.y) * scale + mm.y);
                *(float2*)&S[r1 * SROW + k] = make_float2(
                    (acc[m][j][2] + b1.x) * scale + mm.x,
                    (acc[m][j][3] + b1.y) * scale + mm.y);
            }
        }
        __syncthreads();
    }

    // ---- Phase 2: softmax + attn store (2 rows per warp) ----
    for (int r = 0; r < 2; r++) {
        float* row = S + (wid * 2 + r) * SROW;
        float m = -3.4e38f;
        for (int k = lane; k < NKV; k += 32) m = fmaxf(m, row[k]);
#pragma unroll
        for (int o = 16; o; o >>= 1) m = fmaxf(m, __shfl_xor_sync(0xffffffffu, m, o));
        float s = 0.f;
        for (int k = lane; k < NKV; k += 32) {
            float e = __expf(row[k] - m);
            row[k] = e; s += e;
        }
#pragma unroll
        for (int o = 16; o; o >>= 1) s += __shfl_xor_sync(0xffffffffu, s, o);
        float inv = 1.f / s;
        __syncwarp();
        float* arow = attn + ((size_t)bh * NQ + q0 + wid * 2 + r) * NKV;
        for (int k = lane * 4; k < NKV; k += 128) {
            float4 v = *(float4*)&row[k];
            v.x *= inv; v.y *= inv; v.z *= inv; v.w *= inv;
            *(float4*)&row[k] = v;
            *(float4*)&arow[k] = v;
        }
        __syncwarp();
    }
    __syncthreads();

    // ---- Phase 3: ctx = P @ V, 4 chunks of 256 k, 16-way warp k-split ----
    float acc[2][8][4];
#pragma unroll
    for (int m = 0; m < 2; m++)
#pragma unroll
        for (int j = 0; j < 8; j++)
#pragma unroll
            for (int t = 0; t < 4; t++) acc[m][j][t] = 0.f;

    for (int c = 0; c < 4; c++) {
        ISSUE_CHUNK(VhB, VlB, c);
        CP_WAIT0();
        __syncthreads();
        u32 bufH = sbp + AS_KB, bufL = bufH + KLO;
        int kbase = c * 256 + wid * 16;

        u32 ph[2][4], pl[2][4];
#pragma unroll
        for (int m = 0; m < 2; m++) {
            int r0 = m * 16 + (lane >> 2);
            const float* Sr0 = S + r0 * SROW;
            const float* Sr1 = S + (r0 + 8) * SROW;
            int cc = kbase + (lane & 3) * 2;
            split2(*(const float2*)(Sr0 + cc),     ph[m][0], pl[m][0]);
            split2(*(const float2*)(Sr1 + cc),     ph[m][1], pl[m][1]);
            split2(*(const float2*)(Sr0 + cc + 8), ph[m][2], pl[m][2]);
            split2(*(const float2*)(Sr1 + cc + 8), ph[m][3], pl[m][3]);
        }
#pragma unroll
        for (int dn = 0; dn < 4; dn++) {
            u32 rv = (u32)((wid * 16 + (lane & 15)) * 144 + (dn * 16 + ((lane >> 4) << 3)) * 2);
            u32 vh4[4], vl4[4];
            ldm_x4t(vh4, bufH + rv);
            ldm_x4t(vl4, bufL + rv);
#pragma unroll
            for (int m = 0; m < 2; m++) {
                mma_bf16(acc[m][dn*2],   ph[m], vh4[0], vh4[1]);
                mma_bf16(acc[m][dn*2],   ph[m], vl4[0], vl4[1]);
                mma_bf16(acc[m][dn*2],   pl[m], vh4[0], vh4[1]);
                mma_bf16(acc[m][dn*2+1], ph[m], vh4[2], vh4[3]);
                mma_bf16(acc[m][dn*2+1], ph[m], vl4[2], vl4[3]);
                mma_bf16(acc[m][dn*2+1], pl[m], vh4[2], vh4[3]);
            }
        }
        __syncthreads();
    }

    // slab reduce over 16 warps — reuse S region: slab[w][q(32)][d(64)]
    float* slab = S;
    {
        int qq = lane >> 2;
#pragma unroll
        for (int m = 0; m < 2; m++) {
            int r0 = m * 16 + qq, r1 = r0 + 8;
#pragma unroll
            for (int j = 0; j < 8; j++) {
                int d = j * 8 + (lane & 3) * 2;
                *(float2*)&slab[(wid * 32 + r0) * 64 + d] = make_float2(acc[m][j][0], acc[m][j][1]);
                *(float2*)&slab[(wid * 32 + r1) * 64 + d] = make_float2(acc[m][j][2], acc[m][j][3]);
            }
        }
    }
    __syncthreads();

    {
        int qq = tid >> 4, db = (tid & 15) * 4;
        float s[4] = {0.f, 0.f, 0.f, 0.f};
#pragma unroll
        for (int w = 0; w < 16; w++) {
            const float* p = &slab[(w * 32 + qq) * 64 + db];
#pragma unroll
            for (int t = 0; t < 4; t++) s[t] += p[t];
        }
        size_t e = ((size_t)b * NQ + q0 + qq) * DM + h * DHD + db;
        u32 h0, l0, h1, l1;
        split2(make_float2(s[0], s[1]), h0, l0);
        split2(make_float2(s[2], s[3]), h1, l1);
        *(u32*)((char*)Ch + e * 2)     = h0;
        *(u32*)((char*)Ch + e * 2 + 4) = h1;
        *(u32*)((char*)Cl + e * 2)     = l0;
        *(u32*)((char*)Cl + e * 2 + 4) = l1;
    }
}

// =====================================================================
// launcher
// =====================================================================
extern "C" void kernel_launch(void* const* d_in, const int* in_sizes, int n_in,
                              void* d_out, int out_size)
{
    const float* q    = (const float*)d_in[0];
    const float* kv   = (const float*)d_in[1];
    const int*   mask = (const int*)  d_in[2];
    const float* Wq   = (const float*)d_in[3];
    const float* bq   = (const float*)d_in[4];
    const float* Wk   = (const float*)d_in[5];
    const float* bk   = (const float*)d_in[6];
    const float* Wv   = (const float*)d_in[7];
    const float* bv   = (const float*)d_in[8];
    const float* Wo   = (const float*)d_in[9];
    const float* bo   = (const float*)d_in[10];
    const float* R    = (const float*)d_in[11];

    float* out = (float*)d_out;
    const size_t out_elems  = (size_t)BB*NQ*DM;
    const size_t attn_elems = (size_t)BHN*NQ*NKV;

    __nv_bfloat16 *Qhh, *Qhl, *Khh, *Khl, *Vhh, *Vhl, *Sb;
    __nv_bfloat16 *qh, *ql2, *kvh, *kvl, *ch, *cl, *Wh, *Wl;
    float *attn_fb;
    cudaGetSymbolAddress((void**)&Qhh, g_Qhh);
    cudaGetSymbolAddress((void**)&Qhl, g_Qhl);
    cudaGetSymbolAddress((void**)&Khh, g_Khh);
    cudaGetSymbolAddress((void**)&Khl, g_Khl);
    cudaGetSymbolAddress((void**)&Vhh, g_Vhh);
    cudaGetSymbolAddress((void**)&Vhl, g_Vhl);
    cudaGetSymbolAddress((void**)&Sb,  g_Sb);
    cudaGetSymbolAddress((void**)&qh,  g_qh);
    cudaGetSymbolAddress((void**)&ql2, g_ql);
    cudaGetSymbolAddress((void**)&kvh, g_kvh);
    cudaGetSymbolAddress((void**)&kvl, g_kvl);
    cudaGetSymbolAddress((void**)&ch,  g_ch);
    cudaGetSymbolAddress((void**)&cl,  g_cl);
    cudaGetSymbolAddress((void**)&Wh,  g_Wh);
    cudaGetSymbolAddress((void**)&Wl,  g_Wl);
    cudaGetSymbolAddress((void**)&attn_fb, g_attn_fallback);

    float* attn = ((size_t)out_size >= out_elems + attn_elems)
                ? (out + out_elems) : attn_fb;

    cudaFuncSetAttribute(proj_bf,  cudaFuncAttributeMaxDynamicSharedMemorySize, PROJB_SMEM);
    cudaFuncSetAttribute(bias_mma, cudaFuncAttributeMaxDynamicSharedMemorySize, BIAS_SMEM);
    cudaFuncSetAttribute(attn_mma, cudaFuncAttributeMaxDynamicSharedMemorySize, ATTN_SMEM);

    const size_t WSZ = (size_t)DM * DM;
    cvt<<<4096, 256>>>(q,  qh,  ql2, (int)(out_elems / 4));
    cvt<<<4096, 256>>>(kv, kvh, kvl, (int)(out_elems / 4));
    cvt<<<256, 256>>>(Wq, Wh + 0*WSZ, Wl + 0*WSZ, (int)(WSZ / 4));
    cvt<<<256, 256>>>(Wk, Wh + 1*WSZ, Wl + 1*WSZ, (int)(WSZ / 4));
    cvt<<<256, 256>>>(Wv, Wh + 2*WSZ, Wl + 2*WSZ, (int)(WSZ / 4));
    cvt<<<256, 256>>>(Wo, Wh + 3*WSZ, Wl + 3*WSZ, (int)(WSZ / 4));

    dim3 gProj(4, 64);
    proj_bf<<<gProj, 256, PROJB_SMEM>>>(qh,  ql2, Wh + 0*WSZ, Wl + 0*WSZ, bq, nullptr, Qhh, Qhl, 1);
    proj_bf<<<gProj, 256, PROJB_SMEM>>>(kvh, kvl, Wh + 1*WSZ, Wl + 1*WSZ, bk, nullptr, Khh, Khl, 1);
    proj_bf<<<gProj, 256, PROJB_SMEM>>>(kvh, kvl, Wh + 2*WSZ, Wl + 2*WSZ, bv, nullptr, Vhh, Vhl, 1);

    bias_mma<<<dim3(2, 1024), 256, BIAS_SMEM>>>(Qhh, Qhl, R, Sb);

    attn_mma<<<dim3(64, 32), 512, ATTN_SMEM>>>(Qhh, Qhl, Khh, Khl, Vhh, Vhl,
                                               Sb, mask, attn, ch, cl);

    proj_bf<<<gProj, 256, PROJB_SMEM>>>(ch, cl, Wh + 3*WSZ, Wl + 3*WSZ, bo, out, nullptr, nullptr, 0);
}

// round 15
// speedup vs baseline: 1.0230x; 1.0102x over previous
#include <cuda_runtime.h>
#include <cuda_bf16.h>
#include <cstdint>
#include <cstddef>

#define BB    8
#define HH    8
#define NQ    1024
#define NKV   1024
#define DHD   64
#define DM    512
#define BHN   (BB*HH)

typedef unsigned long long ull;
typedef uint32_t u32;

__device__ __forceinline__ u32 smem_u32(const void* p) {
    u32 a;
    asm("{ .reg .u64 t; cvta.to.shared.u64 t, %1; cvt.u32.u64 %0, t; }" : "=r"(a) : "l"(p));
    return a;
}
__device__ __forceinline__ void ldm_x4(u32* r, u32 a) {
    asm volatile("ldmatrix.sync.aligned.m8n8.x4.shared.b16 {%0,%1,%2,%3}, [%4];"
        : "=r"(r[0]),"=r"(r[1]),"=r"(r[2]),"=r"(r[3]) : "r"(a));
}
__device__ __forceinline__ void ldm_x4t(u32* r, u32 a) {
    asm volatile("ldmatrix.sync.aligned.m8n8.x4.trans.shared.b16 {%0,%1,%2,%3}, [%4];"
        : "=r"(r[0]),"=r"(r[1]),"=r"(r[2]),"=r"(r[3]) : "r"(a));
}
__device__ __forceinline__ void mma_bf16(float* c, const u32* a, u32 b0, u32 b1) {
    asm volatile("mma.sync.aligned.m16n8k16.row.col.f32.bf16.bf16.f32 "
        "{%0,%1,%2,%3}, {%4,%5,%6,%7}, {%8,%9}, {%0,%1,%2,%3};"
        : "+f"(c[0]),"+f"(c[1]),"+f"(c[2]),"+f"(c[3])
        : "r"(a[0]),"r"(a[1]),"r"(a[2]),"r"(a[3]), "r"(b0),"r"(b1));
}
__device__ __forceinline__ void split4(float4 v, ull& hi8, ull& lo8) {
    __nv_bfloat162 h01 = __floats2bfloat162_rn(v.x, v.y);
    __nv_bfloat162 h23 = __floats2bfloat162_rn(v.z, v.w);
    float2 f01 = __bfloat1622float2(h01);
    float2 f23 = __bfloat1622float2(h23);
    __nv_bfloat162 l01 = __floats2bfloat162_rn(v.x - f01.x, v.y - f01.y);
    __nv_bfloat162 l23 = __floats2bfloat162_rn(v.z - f23.x, v.w - f23.y);
    u32 uh0 = *(u32*)&h01, uh1 = *(u32*)&h23;
    u32 ul0 = *(u32*)&l01, ul1 = *(u32*)&l23;
    hi8 = (ull)uh0 | ((ull)uh1 << 32);
    lo8 = (ull)ul0 | ((ull)ul1 << 32);
}
__device__ __forceinline__ void split2(float2 v, u32& h, u32& l) {
    __nv_bfloat162 hb = __floats2bfloat162_rn(v.x, v.y);
    float2 hf = __bfloat1622float2(hb);
    __nv_bfloat162 lb = __floats2bfloat162_rn(v.x - hf.x, v.y - hf.y);
    h = *(u32*)&hb; l = *(u32*)&lb;
}
__device__ __forceinline__ u32 pkbf(float x, float y) {
    __nv_bfloat162 t = __floats2bfloat162_rn(x, y);
    return *(u32*)&t;
}

#define CP_ASYNC16(dst, src) \
    asm volatile("cp.async.ca.shared.global [%0], [%1], 16;" :: "r"(dst), "l"(src) : "memory")
#define CP_COMMIT() asm volatile("cp.async.commit_group;" ::: "memory")
#define CP_WAIT0()  asm volatile("cp.async.wait_group 0;" ::: "memory")
#define CP_WAIT1()  asm volatile("cp.async.wait_group 1;" ::: "memory")

// ---------------- device scratch ----------------
__device__ __nv_bfloat16 g_Qhh[(size_t)BHN*NQ*DHD];
__device__ __nv_bfloat16 g_Qhl[(size_t)BHN*NQ*DHD];
__device__ __nv_bfloat16 g_Khh[(size_t)BHN*NKV*DHD];
__device__ __nv_bfloat16 g_Khl[(size_t)BHN*NKV*DHD];
__device__ __nv_bfloat16 g_Vhh[(size_t)BHN*NKV*DHD];
__device__ __nv_bfloat16 g_Vhl[(size_t)BHN*NKV*DHD];
__device__ __nv_bfloat16 g_Sb[(size_t)NQ*BHN*NKV];
__device__ __nv_bfloat16 g_qh[(size_t)BB*NQ*DM],  g_ql[(size_t)BB*NQ*DM];
__device__ __nv_bfloat16 g_kvh[(size_t)BB*NKV*DM], g_kvl[(size_t)BB*NKV*DM];
__device__ __nv_bfloat16 g_ch[(size_t)BB*NQ*DM],  g_cl[(size_t)BB*NQ*DM];
__device__ __nv_bfloat16 g_Wh[(size_t)4*DM*DM],   g_Wl[(size_t)4*DM*DM];
__device__ float g_attn_fallback[(size_t)BHN*NQ*NKV];

// =====================================================================
// cvt_all: all six fp32->bf16 hi/lo conversions in one launch.
// float4 ranges: [0,1M) q | [1M,2M) kv | [2M, 2M+4*64K) W slabs.
// =====================================================================
#define N4_ACT 1048576
#define N4_W   65536
__global__ void cvt_all(
    const float* __restrict__ q,  const float* __restrict__ kv,
    const float* __restrict__ Wq, const float* __restrict__ Wk,
    const float* __restrict__ Wv, const float* __restrict__ Wo,
    __nv_bfloat16* __restrict__ qh,  __nv_bfloat16* __restrict__ ql,
    __nv_bfloat16* __restrict__ kvh, __nv_bfloat16* __restrict__ kvl,
    __nv_bfloat16* __restrict__ Wh,  __nv_bfloat16* __restrict__ Wl)
{
    int i = blockIdx.x * blockDim.x + threadIdx.x;
    const float* src; __nv_bfloat16 *dh, *dl; int off;
    if (i < N4_ACT)            { src = q;  dh = qh;  dl = ql;  off = i; }
    else if (i < 2*N4_ACT)     { src = kv; dh = kvh; dl = kvl; off = i - N4_ACT; }
    else {
        int j = i - 2*N4_ACT;
        int w = j >> 16; off = j & (N4_W - 1);
        src = (w == 0) ? Wq : (w == 1) ? Wk : (w == 2) ? Wv : Wo;
        dh = Wh + (size_t)w * DM * DM;
        dl = Wl + (size_t)w * DM * DM;
    }
    float4 v = ((const float4*)src)[off];
    ull h8, l8; split4(v, h8, l8);
    ((ull*)dh)[off] = h8;
    ((ull*)dl)[off] = l8;
}

// =====================================================================
// proj_bf: round-13 version (K-chunks of 32, occ 2) — unchanged.
// =====================================================================
#define PB_AH 0
#define PB_AL 10240
#define PB_WH 20480
#define PB_WL 29184
#define PB_STAGE 37888
#define PROJB_SMEM (2*PB_STAGE)

__global__ __launch_bounds__(256, 2) void proj_bf(
    const __nv_bfloat16* __restrict__ Ah, const __nv_bfloat16* __restrict__ Al,
    const __nv_bfloat16* __restrict__ Wh, const __nv_bfloat16* __restrict__ Wl,
    const float* __restrict__ bias, float* __restrict__ C,
    __nv_bfloat16* __restrict__ Ohi, __nv_bfloat16* __restrict__ Olo,
    int permute)
{
    extern __shared__ __align__(128) char smem[];
    u32 sb = smem_u32(smem);
    int tid = threadIdx.x, wid = tid >> 5, lane = tid & 31;
    int m0 = blockIdx.y * 128, n0 = blockIdx.x * 128;
    int wm = wid & 3, wn = wid >> 2;

    int arow = tid >> 2, ac = tid & 3;
    int wrow = tid >> 4, wc16 = tid & 15;

#define PB_ISSUE(kb, buf) do {                                                       \
        u32 base_ = sb + (buf) * PB_STAGE;                                           \
        _Pragma("unroll")                                                            \
        for (int r_ = 0; r_ < 2; r_++) {                                             \
            int row_ = arow + r_ * 64;                                               \
            u32 d_ = base_ + (u32)(row_ * 80 + ac * 16);                             \
            size_t s_ = ((size_t)(m0 + row_) * 512 + (kb) * 32 + ac * 8) * 2;        \
            CP_ASYNC16(d_ + PB_AH, (const char*)Ah + s_);                            \
            CP_ASYNC16(d_ + PB_AL, (const char*)Al + s_);                            \
        }                                                                            \
        _Pragma("unroll")                                                            \
        for (int r_ = 0; r_ < 2; r_++) {                                             \
            int row_ = wrow + r_ * 16;                                               \
            u32 d_ = base_ + (u32)(row_ * 272 + wc16 * 16);                          \
            size_t s_ = ((size_t)((kb) * 32 + row_) * 512 + n0 + wc16 * 8) * 2;      \
            CP_ASYNC16(d_ + PB_WH, (const char*)Wh + s_);                            \
            CP_ASYNC16(d_ + PB_WL, (const char*)Wl + s_);                            \
        }                                                                            \
        CP_COMMIT();                                                                 \
    } while (0)

    float acc[2][8][4];
#pragma unroll
    for (int m = 0; m < 2; m++)
#pragma unroll
        for (int j = 0; j < 8; j++)
#pragma unroll
            for (int t = 0; t < 4; t++) acc[m][j][t] = 0.f;

    PB_ISSUE(0, 0);
    for (int kb = 0; kb < 16; kb++) {
        if (kb < 15) { PB_ISSUE(kb + 1, (kb + 1) & 1); CP_WAIT1(); }
        else CP_WAIT0();
        __syncthreads();
        u32 base = sb + (kb & 1) * PB_STAGE;

#pragma unroll
        for (int ks = 0; ks < 2; ks++) {
            u32 ah[2][4], al[2][4];
#pragma unroll
            for (int f = 0; f < 2; f++) {
                u32 ra = base + PB_AH
                       + (u32)((wm * 32 + f * 16 + (lane & 15)) * 80 + (ks * 16 + ((lane >> 4) << 3)) * 2);
                ldm_x4(ah[f], ra);
                ldm_x4(al[f], ra + (PB_AL - PB_AH));
            }
#pragma unroll
            for (int nf = 0; nf < 4; nf++) {
                u32 rb = base + PB_WH
                       + (u32)((ks * 16 + (lane & 15)) * 272 + (wn * 64 + nf * 16 + ((lane >> 4) << 3)) * 2);
                u32 bh4[4], bl4[4];
                ldm_x4t(bh4, rb);
                ldm_x4t(bl4, rb + (PB_WL - PB_WH));
#pragma unroll
                for (int m = 0; m < 2; m++) {
                    mma_bf16(acc[m][nf*2],   ah[m], bh4[0], bh4[1]);
                    mma_bf16(acc[m][nf*2],   ah[m], bl4[0], bl4[1]);
                    mma_bf16(acc[m][nf*2],   al[m], bh4[0], bh4[1]);
                    mma_bf16(acc[m][nf*2+1], ah[m], bh4[2], bh4[3]);
                    mma_bf16(acc[m][nf*2+1], ah[m], bl4[2], bl4[3]);
                    mma_bf16(acc[m][nf*2+1], al[m], bh4[2], bh4[3]);
                }
            }
        }
        __syncthreads();
    }

    int r0 = m0 + wm * 32 + (lane >> 2);
    int cb = n0 + wn * 64 + (lane & 3) * 2;
#pragma unroll
    for (int m = 0; m < 2; m++) {
#pragma unroll
        for (int j = 0; j < 8; j++) {
            int col = cb + j * 8;
            float2 bv = *(const float2*)&bias[col];
            int rowA = r0 + m * 16, rowB = rowA + 8;
            float2 vA = make_float2(acc[m][j][0] + bv.x, acc[m][j][1] + bv.y);
            float2 vB = make_float2(acc[m][j][2] + bv.x, acc[m][j][3] + bv.y);
            if (permute) {
                int h = col >> 6, dd = col & 63;
                size_t eA = ((size_t)((rowA >> 10) * HH + h) * NQ + (rowA & 1023)) * 64 + dd;
                size_t eB = ((size_t)((rowB >> 10) * HH + h) * NQ + (rowB & 1023)) * 64 + dd;
                u32 hA, lA, hB, lB;
                split2(vA, hA, lA); split2(vB, hB, lB);
                *(u32*)((char*)Ohi + eA * 2) = hA;
                *(u32*)((char*)Olo + eA * 2) = lA;
                *(u32*)((char*)Ohi + eB * 2) = hB;
                *(u32*)((char*)Olo + eB * 2) = lB;
            } else {
                *(float2*)(C + (size_t)rowA * 512 + col) = vA;
                *(float2*)(C + (size_t)rowB * 512 + col) = vB;
            }
        }
    }
}

// =====================================================================
// bias_mma: round-11 version — unchanged.
// =====================================================================
#define BZ_RH 0
#define BZ_QH 36864
#define BZ_QL 46080
#define BIAS_SMEM 55296

__global__ __launch_bounds__(256) void bias_mma(
    const __nv_bfloat16* __restrict__ Qhh, const __nv_bfloat16* __restrict__ Qhl,
    const float* __restrict__ R, __nv_bfloat16* __restrict__ Sb)
{
    extern __shared__ __align__(128) char smem[];
    u32 sb = smem_u32(smem);
    int tid = threadIdx.x, wid = tid >> 5, lane = tid & 31;
    int wm = wid & 3, wn = wid >> 2;
    int q = blockIdx.y, kc = blockIdx.x;

#pragma unroll
    for (int r = 0; r < 2; r++) {
        int idx = tid + r * 256;
        int row = idx >> 3, c4 = idx & 7;
        u32 off = (u32)(row * 144 + c4 * 16);
        size_t e = ((size_t)row * NQ + q) * DHD + c4 * 8;
        *(uint4*)(smem + BZ_QH + off) = *(const uint4*)((const char*)Qhh + e * 2);
        *(uint4*)(smem + BZ_QL + off) = *(const uint4*)((const char*)Qhl + e * 2);
    }
    __syncthreads();

    u32 qh4[4][2][4], ql4[4][2][4];
#pragma unroll
    for (int ks = 0; ks < 4; ks++)
#pragma unroll
        for (int g = 0; g < 2; g++) {
            u32 rb = (u32)((wn * 32 + g * 16 + (lane & 7) + ((lane >> 4) << 3)) * 72
                           + ks * 16 + (((lane >> 3) & 1) << 3)) * 2;
            ldm_x4(qh4[ks][g], sb + BZ_QH + rb);
            ldm_x4(ql4[ks][g], sb + BZ_QL + rb);
        }

    for (int kt = 0; kt < 4; kt++) {
        int k0 = (kc * 4 + kt) * 128;
#pragma unroll
        for (int r = 0; r < 8; r++) {
            int idx = tid + r * 256;
            int row = idx >> 4, col = (idx & 15) << 2;
            float4 v = *(const float4*)(R + ((size_t)q * NKV + k0 + row) * DHD + col);
            u32 p0 = pkbf(v.x, v.y), p1 = pkbf(v.z, v.w);
            *(ull*)(smem + BZ_RH + (row * 72 + col) * 2) = (ull)p0 | ((ull)p1 << 32);
        }
        __syncthreads();

        float acc[2][4][4];
#pragma unroll
        for (int m = 0; m < 2; m++)
#pragma unroll
            for (int j = 0; j < 4; j++)
#pragma unroll
                for (int t = 0; t < 4; t++) acc[m][j][t] = 0.f;

#pragma unroll
        for (int ks = 0; ks < 4; ks++) {
            u32 ah[2][4];
#pragma unroll
            for (int f = 0; f < 2; f++) {
                u32 ra = (u32)((wm * 32 + f * 16 + (lane & 15)) * 72 + ks * 16 + ((lane >> 4) << 3)) * 2;
                ldm_x4(ah[f], sb + BZ_RH + ra);
            }
#pragma unroll
            for (int g = 0; g < 2; g++)
#pragma unroll
                for (int m = 0; m < 2; m++) {
                    mma_bf16(acc[m][g*2],   ah[m], qh4[ks][g][0], qh4[ks][g][1]);
                    mma_bf16(acc[m][g*2],   ah[m], ql4[ks][g][0], ql4[ks][g][1]);
                    mma_bf16(acc[m][g*2+1], ah[m], qh4[ks][g][2], qh4[ks][g][3]);
                    mma_bf16(acc[m][g*2+1], ah[m], ql4[ks][g][2], ql4[ks][g][3]);
                }
        }
        __syncthreads();

        float* T = (float*)smem;
#pragma unroll
        for (int m = 0; m < 2; m++) {
            int krow = wm * 32 + m * 16 + (lane >> 2);
#pragma unroll
            for (int j = 0; j < 4; j++) {
                int bhc = wn * 32 + j * 8 + (lane & 3) * 2;
                T[bhc * 132 + krow]           = acc[m][j][0];
                T[(bhc + 1) * 132 + krow]     = acc[m][j][1];
                T[bhc * 132 + krow + 8]       = acc[m][j][2];
                T[(bhc + 1) * 132 + krow + 8] = acc[m][j][3];
            }
        }
        __syncthreads();

        int bh2 = tid >> 2, part = tid & 3;
        size_t dbase = ((size_t)q * BHN + bh2) * NKV + k0 + part * 32;
#pragma unroll
        for (int j = 0; j < 4; j++) {
            float4 a = *(float4*)&T[bh2 * 132 + part * 32 + j * 8];
            float4 b = *(float4*)&T[bh2 * 132 + part * 32 + j * 8 + 4];
            uint4 o;
            o.x = pkbf(a.x, a.y); o.y = pkbf(a.z, a.w);
            o.z = pkbf(b.x, b.y); o.w = pkbf(b.z, b.w);
            *(uint4*)((char*)Sb + (dbase + j * 8) * 2) = o;
        }
        __syncthreads();
    }
}

// =====================================================================
// attn_mma v3: round-14 version — unchanged.
// =====================================================================
#define SROW  1028
#define AS_MB 131584
#define AS_QH 135680
#define AS_QL 140288
#define AS_KB 144896
#define KLO   36864
#define ATTN_SMEM 218624

__global__ __launch_bounds__(512, 1) void attn_mma(
    const __nv_bfloat16* __restrict__ Qhh, const __nv_bfloat16* __restrict__ Qhl,
    const __nv_bfloat16* __restrict__ Khh, const __nv_bfloat16* __restrict__ Khl,
    const __nv_bfloat16* __restrict__ Vhh, const __nv_bfloat16* __restrict__ Vhl,
    const __nv_bfloat16* __restrict__ Sb,
    const int* __restrict__ mask, float* __restrict__ attn,
    __nv_bfloat16* __restrict__ Ch, __nv_bfloat16* __restrict__ Cl)
{
    extern __shared__ __align__(128) char smem[];
    u32 sbp = smem_u32(smem);
    float* S  = (float*)smem;
    float* mb = (float*)(smem + AS_MB);
    int tid = threadIdx.x, wid = tid >> 5, lane = tid & 31;
    int bh  = blockIdx.x;
    int q0  = blockIdx.y * 32;
    int b = bh >> 3, h = bh & 7;
    const float scale = 0.125f;

    const __nv_bfloat16* KhB = Khh + (size_t)bh * NKV * DHD;
    const __nv_bfloat16* KlB = Khl + (size_t)bh * NKV * DHD;
    const __nv_bfloat16* VhB = Vhh + (size_t)bh * NKV * DHD;
    const __nv_bfloat16* VlB = Vhl + (size_t)bh * NKV * DHD;

    if (tid < 256) {
        int row = tid >> 3, c4 = tid & 7;
        u32 off = (u32)(row * 144 + c4 * 16);
        size_t e = ((size_t)bh * NQ + q0 + row) * DHD + c4 * 8;
        *(uint4*)(smem + AS_QH + off) = *(const uint4*)((const char*)Qhh + e * 2);
        *(uint4*)(smem + AS_QL + off) = *(const uint4*)((const char*)Qhl + e * 2);
    }
    for (int k = tid; k < NKV; k += 512)
        mb[k] = mask[b * NKV + k] ? 0.f : -1e30f;
    __syncthreads();

    u32 qh[4][2][4], ql[4][2][4];
#pragma unroll
    for (int ds = 0; ds < 4; ds++)
#pragma unroll
        for (int m = 0; m < 2; m++) {
            u32 ra = (u32)((m * 16 + (lane & 15)) * 144 + (ds * 16 + ((lane >> 4) << 3)) * 2);
            ldm_x4(qh[ds][m], sbp + AS_QH + ra);
            ldm_x4(ql[ds][m], sbp + AS_QL + ra);
        }

    int prow = tid >> 3, pc4 = tid & 7;
    u32 poff0 = (u32)(prow * 144 + pc4 * 16);
    size_t psrc0 = (size_t)prow * 64 + pc4 * 8;

#define ISSUE_CHUNK(HIptr, LOptr, cix) do {                                        \
        u32 dh_ = sbp + AS_KB;                                                     \
        u32 dl_ = dh_ + KLO;                                                       \
        const char* sh_ = (const char*)((HIptr) + (size_t)(cix) * 256 * 64);       \
        const char* sl_ = (const char*)((LOptr) + (size_t)(cix) * 256 * 64);       \
        _Pragma("unroll")                                                          \
        for (int r_ = 0; r_ < 4; r_++) {                                           \
            u32 o_ = poff0 + (u32)r_ * 64 * 144;                                   \
            size_t s_ = (psrc0 + (size_t)r_ * 64 * 64) * 2;                        \
            CP_ASYNC16(dh_ + o_, sh_ + s_);                                        \
            CP_ASYNC16(dl_ + o_, sl_ + s_);                                        \
        }                                                                          \
        CP_COMMIT();                                                               \
    } while (0)

    for (int c = 0; c < 4; c++) {
        ISSUE_CHUNK(KhB, KlB, c);
        CP_WAIT0();
        __syncthreads();
        u32 bufH = sbp + AS_KB, bufL = bufH + KLO;

        float acc[2][2][4];
#pragma unroll
        for (int m = 0; m < 2; m++)
#pragma unroll
            for (int j = 0; j < 2; j++)
#pragma unroll
                for (int t = 0; t < 4; t++) acc[m][j][t] = 0.f;

#pragma unroll
        for (int ds = 0; ds < 4; ds++) {
            u32 rb = (u32)((wid * 16 + (lane & 15)) * 144 + (ds * 16 + ((lane >> 4) << 3)) * 2);
            u32 kh4[4], kl4[4];
            ldm_x4(kh4, bufH + rb);
            ldm_x4(kl4, bufL + rb);
#pragma unroll
            for (int m = 0; m < 2; m++) {
                mma_bf16(acc[m][0], qh[ds][m], kh4[0], kh4[2]);
                mma_bf16(acc[m][0], qh[ds][m], kl4[0], kl4[2]);
                mma_bf16(acc[m][0], ql[ds][m], kh4[0], kh4[2]);
                mma_bf16(acc[m][1], qh[ds][m], kh4[1], kh4[3]);
                mma_bf16(acc[m][1], qh[ds][m], kl4[1], kl4[3]);
                mma_bf16(acc[m][1], ql[ds][m], kh4[1], kh4[3]);
            }
        }
        int qq = lane >> 2;
#pragma unroll
        for (int m = 0; m < 2; m++) {
            int r0 = m * 16 + qq, r1 = r0 + 8;
#pragma unroll
            for (int j = 0; j < 2; j++) {
                int k = c * 256 + wid * 16 + j * 8 + (lane & 3) * 2;
                u32 u0 = *(const u32*)((const char*)Sb + (((size_t)(q0 + r0) * BHN + bh) * NKV + k) * 2);
                u32 u1 = *(const u32*)((const char*)Sb + (((size_t)(q0 + r1) * BHN + bh) * NKV + k) * 2);
                float2 b0 = __bfloat1622float2(*(__nv_bfloat162*)&u0);
                float2 b1 = __bfloat1622float2(*(__nv_bfloat162*)&u1);
                float2 mm = *(const float2*)&mb[k];
                *(float2*)&S[r0 * SROW + k] = make_float2(
                    (acc[m][j][0] + b0.x) * scale + mm.x,
                    (acc[m][j][1] + b0.y) * scale + mm.y);
                *(float2*)&S[r1 * SROW + k] = make_float2(
                    (acc[m][j][2] + b1.x) * scale + mm.x,
                    (acc[m][j][3] + b1.y) * scale + mm.y);
            }
        }
        __syncthreads();
    }

    for (int r = 0; r < 2; r++) {
        float* row = S + (wid * 2 + r) * SROW;
        float m = -3.4e38f;
        for (int k = lane; k < NKV; k += 32) m = fmaxf(m, row[k]);
#pragma unroll
        for (int o = 16; o; o >>= 1) m = fmaxf(m, __shfl_xor_sync(0xffffffffu, m, o));
        float s = 0.f;
        for (int k = lane; k < NKV; k += 32) {
            float e = __expf(row[k] - m);
            row[k] = e; s += e;
        }
#pragma unroll
        for (int o = 16; o; o >>= 1) s += __shfl_xor_sync(0xffffffffu, s, o);
        float inv = 1.f / s;
        __syncwarp();
        float* arow = attn + ((size_t)bh * NQ + q0 + wid * 2 + r) * NKV;
        for (int k = lane * 4; k < NKV; k += 128) {
            float4 v = *(float4*)&row[k];
            v.x *= inv; v.y *= inv; v.z *= inv; v.w *= inv;
            *(float4*)&row[k] = v;
            *(float4*)&arow[k] = v;
        }
        __syncwarp();
    }
    __syncthreads();

    float acc[2][8][4];
#pragma unroll
    for (int m = 0; m < 2; m++)
#pragma unroll
        for (int j = 0; j < 8; j++)
#pragma unroll
            for (int t = 0; t < 4; t++) acc[m][j][t] = 0.f;

    for (int c = 0; c < 4; c++) {
        ISSUE_CHUNK(VhB, VlB, c);
        CP_WAIT0();
        __syncthreads();
        u32 bufH = sbp + AS_KB, bufL = bufH + KLO;
        int kbase = c * 256 + wid * 16;

        u32 ph[2][4], pl[2][4];
#pragma unroll
        for (int m = 0; m < 2; m++) {
            int r0 = m * 16 + (lane >> 2);
            const float* Sr0 = S + r0 * SROW;
            const float* Sr1 = S + (r0 + 8) * SROW;
            int cc = kbase + (lane & 3) * 2;
            split2(*(const float2*)(Sr0 + cc),     ph[m][0], pl[m][0]);
            split2(*(const float2*)(Sr1 + cc),     ph[m][1], pl[m][1]);
            split2(*(const float2*)(Sr0 + cc + 8), ph[m][2], pl[m][2]);
            split2(*(const float2*)(Sr1 + cc + 8), ph[m][3], pl[m][3]);
        }
#pragma unroll
        for (int dn = 0; dn < 4; dn++) {
            u32 rv = (u32)((wid * 16 + (lane & 15)) * 144 + (dn * 16 + ((lane >> 4) << 3)) * 2);
            u32 vh4[4], vl4[4];
            ldm_x4t(vh4, bufH + rv);
            ldm_x4t(vl4, bufL + rv);
#pragma unroll
            for (int m = 0; m < 2; m++) {
                mma_bf16(acc[m][dn*2],   ph[m], vh4[0], vh4[1]);
                mma_bf16(acc[m][dn*2],   ph[m], vl4[0], vl4[1]);
                mma_bf16(acc[m][dn*2],   pl[m], vh4[0], vh4[1]);
                mma_bf16(acc[m][dn*2+1], ph[m], vh4[2], vh4[3]);
                mma_bf16(acc[m][dn*2+1], ph[m], vl4[2], vl4[3]);
                mma_bf16(acc[m][dn*2+1], pl[m], vh4[2], vh4[3]);
            }
        }
        __syncthreads();
    }

    float* slab = S;
    {
        int qq = lane >> 2;
#pragma unroll
        for (int m = 0; m < 2; m++) {
            int r0 = m * 16 + qq, r1 = r0 + 8;
#pragma unroll
            for (int j = 0; j < 8; j++) {
                int d = j * 8 + (lane & 3) * 2;
                *(float2*)&slab[(wid * 32 + r0) * 64 + d] = make_float2(acc[m][j][0], acc[m][j][1]);
                *(float2*)&slab[(wid * 32 + r1) * 64 + d] = make_float2(acc[m][j][2], acc[m][j][3]);
            }
        }
    }
    __syncthreads();

    {
        int qq = tid >> 4, db = (tid & 15) * 4;
        float s[4] = {0.f, 0.f, 0.f, 0.f};
#pragma unroll
        for (int w = 0; w < 16; w++) {
            const float* p = &slab[(w * 32 + qq) * 64 + db];
#pragma unroll
            for (int t = 0; t < 4; t++) s[t] += p[t];
        }
        size_t e = ((size_t)b * NQ + q0 + qq) * DM + h * DHD + db;
        u32 h0, l0, h1, l1;
        split2(make_float2(s[0], s[1]), h0, l0);
        split2(make_float2(s[2], s[3]), h1, l1);
        *(u32*)((char*)Ch + e * 2)     = h0;
        *(u32*)((char*)Ch + e * 2 + 4) = h1;
        *(u32*)((char*)Cl + e * 2)     = l0;
        *(u32*)((char*)Cl + e * 2 + 4) = l1;
    }
}

// =====================================================================
// launcher
// =====================================================================
extern "C" void kernel_launch(void* const* d_in, const int* in_sizes, int n_in,
                              void* d_out, int out_size)
{
    const float* q    = (const float*)d_in[0];
    const float* kv   = (const float*)d_in[1];
    const int*   mask = (const int*)  d_in[2];
    const float* Wq   = (const float*)d_in[3];
    const float* bq   = (const float*)d_in[4];
    const float* Wk   = (const float*)d_in[5];
    const float* bk   = (const float*)d_in[6];
    const float* Wv   = (const float*)d_in[7];
    const float* bv   = (const float*)d_in[8];
    const float* Wo   = (const float*)d_in[9];
    const float* bo   = (const float*)d_in[10];
    const float* R    = (const float*)d_in[11];

    float* out = (float*)d_out;
    const size_t out_elems  = (size_t)BB*NQ*DM;
    const size_t attn_elems = (size_t)BHN*NQ*NKV;

    __nv_bfloat16 *Qhh, *Qhl, *Khh, *Khl, *Vhh, *Vhl, *Sb;
    __nv_bfloat16 *qh, *ql2, *kvh, *kvl, *ch, *cl, *Wh, *Wl;
    float *attn_fb;
    cudaGetSymbolAddress((void**)&Qhh, g_Qhh);
    cudaGetSymbolAddress((void**)&Qhl, g_Qhl);
    cudaGetSymbolAddress((void**)&Khh, g_Khh);
    cudaGetSymbolAddress((void**)&Khl, g_Khl);
    cudaGetSymbolAddress((void**)&Vhh, g_Vhh);
    cudaGetSymbolAddress((void**)&Vhl, g_Vhl);
    cudaGetSymbolAddress((void**)&Sb,  g_Sb);
    cudaGetSymbolAddress((void**)&qh,  g_qh);
    cudaGetSymbolAddress((void**)&ql2, g_ql);
    cudaGetSymbolAddress((void**)&kvh, g_kvh);
    cudaGetSymbolAddress((void**)&kvl, g_kvl);
    cudaGetSymbolAddress((void**)&ch,  g_ch);
    cudaGetSymbolAddress((void**)&cl,  g_cl);
    cudaGetSymbolAddress((void**)&Wh,  g_Wh);
    cudaGetSymbolAddress((void**)&Wl,  g_Wl);
    cudaGetSymbolAddress((void**)&attn_fb, g_attn_fallback);

    float* attn = ((size_t)out_size >= out_elems + attn_elems)
                ? (out + out_elems) : attn_fb;

    cudaFuncSetAttribute(proj_bf,  cudaFuncAttributeMaxDynamicSharedMemorySize, PROJB_SMEM);
    cudaFuncSetAttribute(bias_mma, cudaFuncAttributeMaxDynamicSharedMemorySize, BIAS_SMEM);
    cudaFuncSetAttribute(attn_mma, cudaFuncAttributeMaxDynamicSharedMemorySize, ATTN_SMEM);

    const size_t WSZ = (size_t)DM * DM;
    // one fused conversion launch: 2*1048576 + 4*65536 float4s
    cvt_all<<<(2*N4_ACT + 4*N4_W) / 256, 256>>>(q, kv, Wq, Wk, Wv, Wo,
                                                qh, ql2, kvh, kvl, Wh, Wl);

    dim3 gProj(4, 64);
    proj_bf<<<gProj, 256, PROJB_SMEM>>>(qh,  ql2, Wh + 0*WSZ, Wl + 0*WSZ, bq, nullptr, Qhh, Qhl, 1);
    proj_bf<<<gProj, 256, PROJB_SMEM>>>(kvh, kvl, Wh + 1*WSZ, Wl + 1*WSZ, bk, nullptr, Khh, Khl, 1);
    proj_bf<<<gProj, 256, PROJB_SMEM>>>(kvh, kvl, Wh + 2*WSZ, Wl + 2*WSZ, bv, nullptr, Vhh, Vhl, 1);

    bias_mma<<<dim3(2, 1024), 256, BIAS_SMEM>>>(Qhh, Qhl, R, Sb);

    attn_mma<<<dim3(64, 32), 512, ATTN_SMEM>>>(Qhh, Qhl, Khh, Khl, Vhh, Vhl,
                                               Sb, mask, attn, ch, cl);

    proj_bf<<<gProj, 256, PROJB_SMEM>>>(ch, cl, Wh + 3*WSZ, Wl + 3*WSZ, bo, out, nullptr, nullptr, 0);
}

// round 16
// speedup vs baseline: 1.1627x; 1.1366x over previous
#include <cuda_runtime.h>
#include <cuda_bf16.h>
#include <cstdint>
#include <cstddef>

#define BB    8
#define HH    8
#define NQ    1024
#define NKV   1024
#define DHD   64
#define DM    512
#define BHN   (BB*HH)

typedef unsigned long long ull;
typedef uint32_t u32;

__device__ __forceinline__ u32 smem_u32(const void* p) {
    u32 a;
    asm("{ .reg .u64 t; cvta.to.shared.u64 t, %1; cvt.u32.u64 %0, t; }" : "=r"(a) : "l"(p));
    return a;
}
__device__ __forceinline__ void ldm_x4(u32* r, u32 a) {
    asm volatile("ldmatrix.sync.aligned.m8n8.x4.shared.b16 {%0,%1,%2,%3}, [%4];"
        : "=r"(r[0]),"=r"(r[1]),"=r"(r[2]),"=r"(r[3]) : "r"(a));
}
__device__ __forceinline__ void ldm_x4t(u32* r, u32 a) {
    asm volatile("ldmatrix.sync.aligned.m8n8.x4.trans.shared.b16 {%0,%1,%2,%3}, [%4];"
        : "=r"(r[0]),"=r"(r[1]),"=r"(r[2]),"=r"(r[3]) : "r"(a));
}
__device__ __forceinline__ void mma_bf16(float* c, const u32* a, u32 b0, u32 b1) {
    asm volatile("mma.sync.aligned.m16n8k16.row.col.f32.bf16.bf16.f32 "
        "{%0,%1,%2,%3}, {%4,%5,%6,%7}, {%8,%9}, {%0,%1,%2,%3};"
        : "+f"(c[0]),"+f"(c[1]),"+f"(c[2]),"+f"(c[3])
        : "r"(a[0]),"r"(a[1]),"r"(a[2]),"r"(a[3]), "r"(b0),"r"(b1));
}
__device__ __forceinline__ void split4(float4 v, ull& hi8, ull& lo8) {
    __nv_bfloat162 h01 = __floats2bfloat162_rn(v.x, v.y);
    __nv_bfloat162 h23 = __floats2bfloat162_rn(v.z, v.w);
    float2 f01 = __bfloat1622float2(h01);
    float2 f23 = __bfloat1622float2(h23);
    __nv_bfloat162 l01 = __floats2bfloat162_rn(v.x - f01.x, v.y - f01.y);
    __nv_bfloat162 l23 = __floats2bfloat162_rn(v.z - f23.x, v.w - f23.y);
    u32 uh0 = *(u32*)&h01, uh1 = *(u32*)&h23;
    u32 ul0 = *(u32*)&l01, ul1 = *(u32*)&l23;
    hi8 = (ull)uh0 | ((ull)uh1 << 32);
    lo8 = (ull)ul0 | ((ull)ul1 << 32);
}
__device__ __forceinline__ void split2(float2 v, u32& h, u32& l) {
    __nv_bfloat162 hb = __floats2bfloat162_rn(v.x, v.y);
    float2 hf = __bfloat1622float2(hb);
    __nv_bfloat162 lb = __floats2bfloat162_rn(v.x - hf.x, v.y - hf.y);
    h = *(u32*)&hb; l = *(u32*)&lb;
}
__device__ __forceinline__ u32 pkbf(float x, float y) {
    __nv_bfloat162 t = __floats2bfloat162_rn(x, y);
    return *(u32*)&t;
}

#define CP_ASYNC16(dst, src) \
    asm volatile("cp.async.ca.shared.global [%0], [%1], 16;" :: "r"(dst), "l"(src) : "memory")
#define CP_COMMIT() asm volatile("cp.async.commit_group;" ::: "memory")
#define CP_WAIT0()  asm volatile("cp.async.wait_group 0;" ::: "memory")
#define CP_WAIT1()  asm volatile("cp.async.wait_group 1;" ::: "memory")

// ---------------- device scratch ----------------
__device__ __nv_bfloat16 g_Qhh[(size_t)BHN*NQ*DHD];
__device__ __nv_bfloat16 g_Qhl[(size_t)BHN*NQ*DHD];
__device__ __nv_bfloat16 g_Khh[(size_t)BHN*NKV*DHD];
__device__ __nv_bfloat16 g_Khl[(size_t)BHN*NKV*DHD];
__device__ __nv_bfloat16 g_Vhh[(size_t)BHN*NKV*DHD];
__device__ __nv_bfloat16 g_Vhl[(size_t)BHN*NKV*DHD];
__device__ __nv_bfloat16 g_Sb[(size_t)NQ*BHN*NKV];
__device__ __nv_bfloat16 g_qh[(size_t)BB*NQ*DM],  g_ql[(size_t)BB*NQ*DM];
__device__ __nv_bfloat16 g_kvh[(size_t)BB*NKV*DM], g_kvl[(size_t)BB*NKV*DM];
__device__ __nv_bfloat16 g_ch[(size_t)BB*NQ*DM],  g_cl[(size_t)BB*NQ*DM];
__device__ __nv_bfloat16 g_Wh[(size_t)4*DM*DM],   g_Wl[(size_t)4*DM*DM];
__device__ int g_idx[BB*NKV];
__device__ int g_cnt[BB];
__device__ float g_attn_fallback[(size_t)BHN*NQ*NKV];

// =====================================================================
// compact: deterministic per-b active-column index list (padded to 256).
// grid 8, block 1024.
// =====================================================================
__global__ void compact_mask(const int* __restrict__ mask, int* __restrict__ idx,
                             int* __restrict__ cnt)
{
    __shared__ int wcnt[32];
    int b = blockIdx.x, k = threadIdx.x;
    int active = mask[b * NKV + k] != 0;
    unsigned bal = __ballot_sync(0xffffffffu, active);
    int wid = k >> 5, lane = k & 31;
    if (lane == 0) wcnt[wid] = __popc(bal);
    __syncthreads();
    int base = 0;
    for (int w = 0; w < wid; w++) base += wcnt[w];
    int pos = base + __popc(bal & ((1u << lane) - 1u));
    if (active) idx[b * NKV + pos] = k;
    __syncthreads();
    if (k == 0) {
        int tot = 0;
        for (int w = 0; w < 32; w++) tot += wcnt[w];
        cnt[b] = tot;
        int pad = (tot + 255) & ~255;
        for (int i = tot; i < pad; i++) idx[b * NKV + i] = 0;
    }
}

// =====================================================================
// cvt_all: unchanged (round-15).
// =====================================================================
#define N4_ACT 1048576
#define N4_W   65536
__global__ void cvt_all(
    const float* __restrict__ q,  const float* __restrict__ kv,
    const float* __restrict__ Wq, const float* __restrict__ Wk,
    const float* __restrict__ Wv, const float* __restrict__ Wo,
    __nv_bfloat16* __restrict__ qh,  __nv_bfloat16* __restrict__ ql,
    __nv_bfloat16* __restrict__ kvh, __nv_bfloat16* __restrict__ kvl,
    __nv_bfloat16* __restrict__ Wh,  __nv_bfloat16* __restrict__ Wl)
{
    int i = blockIdx.x * blockDim.x + threadIdx.x;
    const float* src; __nv_bfloat16 *dh, *dl; int off;
    if (i < N4_ACT)            { src = q;  dh = qh;  dl = ql;  off = i; }
    else if (i < 2*N4_ACT)     { src = kv; dh = kvh; dl = kvl; off = i - N4_ACT; }
    else {
        int j = i - 2*N4_ACT;
        int w = j >> 16; off = j & (N4_W - 1);
        src = (w == 0) ? Wq : (w == 1) ? Wk : (w == 2) ? Wv : Wo;
        dh = Wh + (size_t)w * DM * DM;
        dl = Wl + (size_t)w * DM * DM;
    }
    float4 v = ((const float4*)src)[off];
    ull h8, l8; split4(v, h8, l8);
    ((ull*)dh)[off] = h8;
    ((ull*)dl)[off] = l8;
}

// =====================================================================
// proj_bf: unchanged (round-15).
// =====================================================================
#define PB_AH 0
#define PB_AL 10240
#define PB_WH 20480
#define PB_WL 29184
#define PB_STAGE 37888
#define PROJB_SMEM (2*PB_STAGE)

__global__ __launch_bounds__(256, 2) void proj_bf(
    const __nv_bfloat16* __restrict__ Ah, const __nv_bfloat16* __restrict__ Al,
    const __nv_bfloat16* __restrict__ Wh, const __nv_bfloat16* __restrict__ Wl,
    const float* __restrict__ bias, float* __restrict__ C,
    __nv_bfloat16* __restrict__ Ohi, __nv_bfloat16* __restrict__ Olo,
    int permute)
{
    extern __shared__ __align__(128) char smem[];
    u32 sb = smem_u32(smem);
    int tid = threadIdx.x, wid = tid >> 5, lane = tid & 31;
    int m0 = blockIdx.y * 128, n0 = blockIdx.x * 128;
    int wm = wid & 3, wn = wid >> 2;

    int arow = tid >> 2, ac = tid & 3;
    int wrow = tid >> 4, wc16 = tid & 15;

#define PB_ISSUE(kb, buf) do {                                                       \
        u32 base_ = sb + (buf) * PB_STAGE;                                           \
        _Pragma("unroll")                                                            \
        for (int r_ = 0; r_ < 2; r_++) {                                             \
            int row_ = arow + r_ * 64;                                               \
            u32 d_ = base_ + (u32)(row_ * 80 + ac * 16);                             \
            size_t s_ = ((size_t)(m0 + row_) * 512 + (kb) * 32 + ac * 8) * 2;        \
            CP_ASYNC16(d_ + PB_AH, (const char*)Ah + s_);                            \
            CP_ASYNC16(d_ + PB_AL, (const char*)Al + s_);                            \
        }                                                                            \
        _Pragma("unroll")                                                            \
        for (int r_ = 0; r_ < 2; r_++) {                                             \
            int row_ = wrow + r_ * 16;                                               \
            u32 d_ = base_ + (u32)(row_ * 272 + wc16 * 16);                          \
            size_t s_ = ((size_t)((kb) * 32 + row_) * 512 + n0 + wc16 * 8) * 2;      \
            CP_ASYNC16(d_ + PB_WH, (const char*)Wh + s_);                            \
            CP_ASYNC16(d_ + PB_WL, (const char*)Wl + s_);                            \
        }                                                                            \
        CP_COMMIT();                                                                 \
    } while (0)

    float acc[2][8][4];
#pragma unroll
    for (int m = 0; m < 2; m++)
#pragma unroll
        for (int j = 0; j < 8; j++)
#pragma unroll
            for (int t = 0; t < 4; t++) acc[m][j][t] = 0.f;

    PB_ISSUE(0, 0);
    for (int kb = 0; kb < 16; kb++) {
        if (kb < 15) { PB_ISSUE(kb + 1, (kb + 1) & 1); CP_WAIT1(); }
        else CP_WAIT0();
        __syncthreads();
        u32 base = sb + (kb & 1) * PB_STAGE;

#pragma unroll
        for (int ks = 0; ks < 2; ks++) {
            u32 ah[2][4], al[2][4];
#pragma unroll
            for (int f = 0; f < 2; f++) {
                u32 ra = base + PB_AH
                       + (u32)((wm * 32 + f * 16 + (lane & 15)) * 80 + (ks * 16 + ((lane >> 4) << 3)) * 2);
                ldm_x4(ah[f], ra);
                ldm_x4(al[f], ra + (PB_AL - PB_AH));
            }
#pragma unroll
            for (int nf = 0; nf < 4; nf++) {
                u32 rb = base + PB_WH
                       + (u32)((ks * 16 + (lane & 15)) * 272 + (wn * 64 + nf * 16 + ((lane >> 4) << 3)) * 2);
                u32 bh4[4], bl4[4];
                ldm_x4t(bh4, rb);
                ldm_x4t(bl4, rb + (PB_WL - PB_WH));
#pragma unroll
                for (int m = 0; m < 2; m++) {
                    mma_bf16(acc[m][nf*2],   ah[m], bh4[0], bh4[1]);
                    mma_bf16(acc[m][nf*2],   ah[m], bl4[0], bl4[1]);
                    mma_bf16(acc[m][nf*2],   al[m], bh4[0], bh4[1]);
                    mma_bf16(acc[m][nf*2+1], ah[m], bh4[2], bh4[3]);
                    mma_bf16(acc[m][nf*2+1], ah[m], bl4[2], bl4[3]);
                    mma_bf16(acc[m][nf*2+1], al[m], bh4[2], bh4[3]);
                }
            }
        }
        __syncthreads();
    }

    int r0 = m0 + wm * 32 + (lane >> 2);
    int cb = n0 + wn * 64 + (lane & 3) * 2;
#pragma unroll
    for (int m = 0; m < 2; m++) {
#pragma unroll
        for (int j = 0; j < 8; j++) {
            int col = cb + j * 8;
            float2 bv = *(const float2*)&bias[col];
            int rowA = r0 + m * 16, rowB = rowA + 8;
            float2 vA = make_float2(acc[m][j][0] + bv.x, acc[m][j][1] + bv.y);
            float2 vB = make_float2(acc[m][j][2] + bv.x, acc[m][j][3] + bv.y);
            if (permute) {
                int h = col >> 6, dd = col & 63;
                size_t eA = ((size_t)((rowA >> 10) * HH + h) * NQ + (rowA & 1023)) * 64 + dd;
                size_t eB = ((size_t)((rowB >> 10) * HH + h) * NQ + (rowB & 1023)) * 64 + dd;
                u32 hA, lA, hB, lB;
                split2(vA, hA, lA); split2(vB, hB, lB);
                *(u32*)((char*)Ohi + eA * 2) = hA;
                *(u32*)((char*)Olo + eA * 2) = lA;
                *(u32*)((char*)Ohi + eB * 2) = hB;
                *(u32*)((char*)Olo + eB * 2) = lB;
            } else {
                *(float2*)(C + (size_t)rowA * 512 + col) = vA;
                *(float2*)(C + (size_t)rowB * 512 + col) = vB;
            }
        }
    }
}

// =====================================================================
// bias_mma: unchanged (round-15).
// =====================================================================
#define BZ_RH 0
#define BZ_QH 36864
#define BZ_QL 46080
#define BIAS_SMEM 55296

__global__ __launch_bounds__(256) void bias_mma(
    const __nv_bfloat16* __restrict__ Qhh, const __nv_bfloat16* __restrict__ Qhl,
    const float* __restrict__ R, __nv_bfloat16* __restrict__ Sb)
{
    extern __shared__ __align__(128) char smem[];
    u32 sb = smem_u32(smem);
    int tid = threadIdx.x, wid = tid >> 5, lane = tid & 31;
    int wm = wid & 3, wn = wid >> 2;
    int q = blockIdx.y, kc = blockIdx.x;

#pragma unroll
    for (int r = 0; r < 2; r++) {
        int idx = tid + r * 256;
        int row = idx >> 3, c4 = idx & 7;
        u32 off = (u32)(row * 144 + c4 * 16);
        size_t e = ((size_t)row * NQ + q) * DHD + c4 * 8;
        *(uint4*)(smem + BZ_QH + off) = *(const uint4*)((const char*)Qhh + e * 2);
        *(uint4*)(smem + BZ_QL + off) = *(const uint4*)((const char*)Qhl + e * 2);
    }
    __syncthreads();

    u32 qh4[4][2][4], ql4[4][2][4];
#pragma unroll
    for (int ks = 0; ks < 4; ks++)
#pragma unroll
        for (int g = 0; g < 2; g++) {
            u32 rb = (u32)((wn * 32 + g * 16 + (lane & 7) + ((lane >> 4) << 3)) * 72
                           + ks * 16 + (((lane >> 3) & 1) << 3)) * 2;
            ldm_x4(qh4[ks][g], sb + BZ_QH + rb);
            ldm_x4(ql4[ks][g], sb + BZ_QL + rb);
        }

    for (int kt = 0; kt < 4; kt++) {
        int k0 = (kc * 4 + kt) * 128;
#pragma unroll
        for (int r = 0; r < 8; r++) {
            int idx = tid + r * 256;
            int row = idx >> 4, col = (idx & 15) << 2;
            float4 v = *(const float4*)(R + ((size_t)q * NKV + k0 + row) * DHD + col);
            u32 p0 = pkbf(v.x, v.y), p1 = pkbf(v.z, v.w);
            *(ull*)(smem + BZ_RH + (row * 72 + col) * 2) = (ull)p0 | ((ull)p1 << 32);
        }
        __syncthreads();

        float acc[2][4][4];
#pragma unroll
        for (int m = 0; m < 2; m++)
#pragma unroll
            for (int j = 0; j < 4; j++)
#pragma unroll
                for (int t = 0; t < 4; t++) acc[m][j][t] = 0.f;

#pragma unroll
        for (int ks = 0; ks < 4; ks++) {
            u32 ah[2][4];
#pragma unroll
            for (int f = 0; f < 2; f++) {
                u32 ra = (u32)((wm * 32 + f * 16 + (lane & 15)) * 72 + ks * 16 + ((lane >> 4) << 3)) * 2;
                ldm_x4(ah[f], sb + BZ_RH + ra);
            }
#pragma unroll
            for (int g = 0; g < 2; g++)
#pragma unroll
                for (int m = 0; m < 2; m++) {
                    mma_bf16(acc[m][g*2],   ah[m], qh4[ks][g][0], qh4[ks][g][1]);
                    mma_bf16(acc[m][g*2],   ah[m], ql4[ks][g][0], ql4[ks][g][1]);
                    mma_bf16(acc[m][g*2+1], ah[m], qh4[ks][g][2], qh4[ks][g][3]);
                    mma_bf16(acc[m][g*2+1], ah[m], ql4[ks][g][2], ql4[ks][g][3]);
                }
        }
        __syncthreads();

        float* T = (float*)smem;
#pragma unroll
        for (int m = 0; m < 2; m++) {
            int krow = wm * 32 + m * 16 + (lane >> 2);
#pragma unroll
            for (int j = 0; j < 4; j++) {
                int bhc = wn * 32 + j * 8 + (lane & 3) * 2;
                T[bhc * 132 + krow]           = acc[m][j][0];
                T[(bhc + 1) * 132 + krow]     = acc[m][j][1];
                T[bhc * 132 + krow + 8]       = acc[m][j][2];
                T[(bhc + 1) * 132 + krow + 8] = acc[m][j][3];
            }
        }
        __syncthreads();

        int bh2 = tid >> 2, part = tid & 3;
        size_t dbase = ((size_t)q * BHN + bh2) * NKV + k0 + part * 32;
#pragma unroll
        for (int j = 0; j < 4; j++) {
            float4 a = *(float4*)&T[bh2 * 132 + part * 32 + j * 8];
            float4 b = *(float4*)&T[bh2 * 132 + part * 32 + j * 8 + 4];
            uint4 o;
            o.x = pkbf(a.x, a.y); o.y = pkbf(a.z, a.w);
            o.z = pkbf(b.x, b.y); o.w = pkbf(b.z, b.w);
            *(uint4*)((char*)Sb + (dbase + j * 8) * 2) = o;
        }
        __syncthreads();
    }
}

// =====================================================================
// attn_mma v4: masked-column compaction. q-tile 32, 512 threads.
// smem: S[32][1028] 131584 | QH 4608 | QL 4608 | KV hi 36864 | lo 36864 |
//       ilist 4096 -> 218624.
// =====================================================================
#define SROW  1028
#define AS_QH 131584
#define AS_QL 136192
#define AS_KB 140800
#define KLO   36864
#define AS_IL 214528
#define ATTN_SMEM 218624

__global__ __launch_bounds__(512, 1) void attn_mma(
    const __nv_bfloat16* __restrict__ Qhh, const __nv_bfloat16* __restrict__ Qhl,
    const __nv_bfloat16* __restrict__ Khh, const __nv_bfloat16* __restrict__ Khl,
    const __nv_bfloat16* __restrict__ Vhh, const __nv_bfloat16* __restrict__ Vhl,
    const __nv_bfloat16* __restrict__ Sb,
    const int* __restrict__ gidx, const int* __restrict__ gcnt,
    float* __restrict__ attn,
    __nv_bfloat16* __restrict__ Ch, __nv_bfloat16* __restrict__ Cl)
{
    extern __shared__ __align__(128) char smem[];
    u32 sbp = smem_u32(smem);
    float* S   = (float*)smem;
    int* ilist = (int*)(smem + AS_IL);
    int tid = threadIdx.x, wid = tid >> 5, lane = tid & 31;
    int bh  = blockIdx.x;
    int q0  = blockIdx.y * 32;
    int b = bh >> 3, h = bh & 7;
    const float scale = 0.125f;

    int cnt = gcnt[b];
    int nch = (cnt + 255) >> 8;

    const __nv_bfloat16* KhB = Khh + (size_t)bh * NKV * DHD;
    const __nv_bfloat16* KlB = Khl + (size_t)bh * NKV * DHD;
    const __nv_bfloat16* VhB = Vhh + (size_t)bh * NKV * DHD;
    const __nv_bfloat16* VlB = Vhl + (size_t)bh * NKV * DHD;

    if (tid < 256) {
        int row = tid >> 3, c4 = tid & 7;
        u32 off = (u32)(row * 144 + c4 * 16);
        size_t e = ((size_t)bh * NQ + q0 + row) * DHD + c4 * 8;
        *(uint4*)(smem + AS_QH + off) = *(const uint4*)((const char*)Qhh + e * 2);
        *(uint4*)(smem + AS_QL + off) = *(const uint4*)((const char*)Qhl + e * 2);
    }
    for (int k = tid; k < NKV; k += 512)
        ilist[k] = gidx[b * NKV + k];
    // prefill S with -1e30 (masked columns keep it; actives overwritten)
    for (int i = tid; i < 32 * 1024; i += 512)
        S[(i >> 10) * SROW + (i & 1023)] = -1e30f;
    __syncthreads();

    u32 qh[4][2][4], ql[4][2][4];
#pragma unroll
    for (int ds = 0; ds < 4; ds++)
#pragma unroll
        for (int m = 0; m < 2; m++) {
            u32 ra = (u32)((m * 16 + (lane & 15)) * 144 + (ds * 16 + ((lane >> 4) << 3)) * 2);
            ldm_x4(qh[ds][m], sbp + AS_QH + ra);
            ldm_x4(ql[ds][m], sbp + AS_QL + ra);
        }

    int prow = tid >> 3, pc4 = tid & 7;
    u32 poff0 = (u32)(prow * 144 + pc4 * 16);

#define ISSUE_CHUNK(HIptr, LOptr, cix) do {                                        \
        u32 dh_ = sbp + AS_KB;                                                     \
        u32 dl_ = dh_ + KLO;                                                       \
        _Pragma("unroll")                                                          \
        for (int r_ = 0; r_ < 4; r_++) {                                           \
            int row_ = prow + r_ * 64;                                             \
            int krow_ = ilist[(cix) * 256 + row_];                                 \
            u32 o_ = poff0 + (u32)r_ * 64 * 144;                                   \
            size_t s_ = ((size_t)krow_ * 64 + pc4 * 8) * 2;                        \
            CP_ASYNC16(dh_ + o_, (const char*)(HIptr) + s_);                       \
            CP_ASYNC16(dl_ + o_, (const char*)(LOptr) + s_);                       \
        }                                                                          \
        CP_COMMIT();                                                               \
    } while (0)

    // ---- Phase 1: QK^T + Sb on active columns, scatter into S ----
    for (int c = 0; c < nch; c++) {
        ISSUE_CHUNK(KhB, KlB, c);
        CP_WAIT0();
        __syncthreads();
        u32 bufH = sbp + AS_KB, bufL = bufH + KLO;

        float acc[2][2][4];
#pragma unroll
        for (int m = 0; m < 2; m++)
#pragma unroll
            for (int j = 0; j < 2; j++)
#pragma unroll
                for (int t = 0; t < 4; t++) acc[m][j][t] = 0.f;

#pragma unroll
        for (int ds = 0; ds < 4; ds++) {
            u32 rb = (u32)((wid * 16 + (lane & 15)) * 144 + (ds * 16 + ((lane >> 4) << 3)) * 2);
            u32 kh4[4], kl4[4];
            ldm_x4(kh4, bufH + rb);
            ldm_x4(kl4, bufL + rb);
#pragma unroll
            for (int m = 0; m < 2; m++) {
                mma_bf16(acc[m][0], qh[ds][m], kh4[0], kh4[2]);
                mma_bf16(acc[m][0], qh[ds][m], kl4[0], kl4[2]);
                mma_bf16(acc[m][0], ql[ds][m], kh4[0], kh4[2]);
                mma_bf16(acc[m][1], qh[ds][m], kh4[1], kh4[3]);
                mma_bf16(acc[m][1], qh[ds][m], kl4[1], kl4[3]);
                mma_bf16(acc[m][1], ql[ds][m], kh4[1], kh4[3]);
            }
        }
        int qq = lane >> 2;
#pragma unroll
        for (int j = 0; j < 2; j++) {
            int cc = c * 256 + wid * 16 + j * 8 + (lane & 3) * 2;
#pragma unroll
            for (int e = 0; e < 2; e++) {
                int cce = cc + e;
                int act = cce < cnt;
                int kg  = act ? ilist[cce] : 0;     // gather (Sb) index
                int kt  = act ? kg : 1024;          // scatter target (dead slot)
#pragma unroll
                for (int m = 0; m < 2; m++) {
                    int r0 = m * 16 + qq, r1 = r0 + 8;
                    float b0 = __bfloat162float(Sb[((size_t)(q0 + r0) * BHN + bh) * NKV + kg]);
                    float b1 = __bfloat162float(Sb[((size_t)(q0 + r1) * BHN + bh) * NKV + kg]);
                    S[r0 * SROW + kt] = (acc[m][j][e]     + b0) * scale;
                    S[r1 * SROW + kt] = (acc[m][j][2 + e] + b1) * scale;
                }
            }
        }
        __syncthreads();
    }

    // ---- Phase 2: softmax + attn store (full rows; masked -> exact 0) ----
    for (int r = 0; r < 2; r++) {
        float* row = S + (wid * 2 + r) * SROW;
        float m = -3.4e38f;
        for (int k = lane; k < NKV; k += 32) m = fmaxf(m, row[k]);
#pragma unroll
        for (int o = 16; o; o >>= 1) m = fmaxf(m, __shfl_xor_sync(0xffffffffu, m, o));
        float s = 0.f;
        for (int k = lane; k < NKV; k += 32) {
            float e = __expf(row[k] - m);
            row[k] = e; s += e;
        }
#pragma unroll
        for (int o = 16; o; o >>= 1) s += __shfl_xor_sync(0xffffffffu, s, o);
        float inv = 1.f / s;
        __syncwarp();
        float* arow = attn + ((size_t)bh * NQ + q0 + wid * 2 + r) * NKV;
        for (int k = lane * 4; k < NKV; k += 128) {
            float4 v = *(float4*)&row[k];
            v.x *= inv; v.y *= inv; v.z *= inv; v.w *= inv;
            *(float4*)&row[k] = v;
            *(float4*)&arow[k] = v;
        }
        if (lane < 2) row[1024] = 0.f;   // will re-zero below; dead slot
        __syncwarp();
    }
    // zero dead slots (padding P reads)
    if (tid < 32) S[tid * SROW + 1024] = 0.f;
    __syncthreads();

    // ---- Phase 3: ctx = P @ V over active columns ----
    float acc[2][8][4];
#pragma unroll
    for (int m = 0; m < 2; m++)
#pragma unroll
        for (int j = 0; j < 8; j++)
#pragma unroll
            for (int t = 0; t < 4; t++) acc[m][j][t] = 0.f;

    for (int c = 0; c < nch; c++) {
        ISSUE_CHUNK(VhB, VlB, c);
        CP_WAIT0();
        __syncthreads();
        u32 bufH = sbp + AS_KB, bufL = bufH + KLO;
        int kbase = c * 256 + wid * 16;

        int kt[4];
        {
            int cc0 = kbase + (lane & 3) * 2;
#pragma unroll
            for (int e = 0; e < 4; e++) {
                int cce = cc0 + (e >> 1) * 8 + (e & 1);
                kt[e] = (cce < cnt) ? ilist[cce] : 1024;
            }
        }
        u32 ph[2][4], pl[2][4];
#pragma unroll
        for (int m = 0; m < 2; m++) {
            int r0 = m * 16 + (lane >> 2), r1 = r0 + 8;
            const float* Sr0 = S + r0 * SROW;
            const float* Sr1 = S + r1 * SROW;
            split2(make_float2(Sr0[kt[0]], Sr0[kt[1]]), ph[m][0], pl[m][0]);
            split2(make_float2(Sr1[kt[0]], Sr1[kt[1]]), ph[m][1], pl[m][1]);
            split2(make_float2(Sr0[kt[2]], Sr0[kt[3]]), ph[m][2], pl[m][2]);
            split2(make_float2(Sr1[kt[2]], Sr1[kt[3]]), ph[m][3], pl[m][3]);
        }
#pragma unroll
        for (int dn = 0; dn < 4; dn++) {
            u32 rv = (u32)((wid * 16 + (lane & 15)) * 144 + (dn * 16 + ((lane >> 4) << 3)) * 2);
            u32 vh4[4], vl4[4];
            ldm_x4t(vh4, bufH + rv);
            ldm_x4t(vl4, bufL + rv);
#pragma unroll
            for (int m = 0; m < 2; m++) {
                mma_bf16(acc[m][dn*2],   ph[m], vh4[0], vh4[1]);
                mma_bf16(acc[m][dn*2],   ph[m], vl4[0], vl4[1]);
                mma_bf16(acc[m][dn*2],   pl[m], vh4[0], vh4[1]);
                mma_bf16(acc[m][dn*2+1], ph[m], vh4[2], vh4[3]);
                mma_bf16(acc[m][dn*2+1], ph[m], vl4[2], vl4[3]);
                mma_bf16(acc[m][dn*2+1], pl[m], vh4[2], vh4[3]);
            }
        }
        __syncthreads();
    }

    // slab reduce over 16 warps — reuse S region
    float* slab = S;
    {
        int qq = lane >> 2;
#pragma unroll
        for (int m = 0; m < 2; m++) {
            int r0 = m * 16 + qq, r1 = r0 + 8;
#pragma unroll
            for (int j = 0; j < 8; j++) {
                int d = j * 8 + (lane & 3) * 2;
                *(float2*)&slab[(wid * 32 + r0) * 64 + d] = make_float2(acc[m][j][0], acc[m][j][1]);
                *(float2*)&slab[(wid * 32 + r1) * 64 + d] = make_float2(acc[m][j][2], acc[m][j][3]);
            }
        }
    }
    __syncthreads();

    {
        int qq = tid >> 4, db = (tid & 15) * 4;
        float s[4] = {0.f, 0.f, 0.f, 0.f};
#pragma unroll
        for (int w = 0; w < 16; w++) {
            const float* p = &slab[(w * 32 + qq) * 64 + db];
#pragma unroll
            for (int t = 0; t < 4; t++) s[t] += p[t];
        }
        size_t e = ((size_t)b * NQ + q0 + qq) * DM + h * DHD + db;
        u32 h0, l0, h1, l1;
        split2(make_float2(s[0], s[1]), h0, l0);
        split2(make_float2(s[2], s[3]), h1, l1);
        *(u32*)((char*)Ch + e * 2)     = h0;
        *(u32*)((char*)Ch + e * 2 + 4) = h1;
        *(u32*)((char*)Cl + e * 2)     = l0;
        *(u32*)((char*)Cl + e * 2 + 4) = l1;
    }
}

// =====================================================================
// launcher
// =====================================================================
extern "C" void kernel_launch(void* const* d_in, const int* in_sizes, int n_in,
                              void* d_out, int out_size)
{
    const float* q    = (const float*)d_in[0];
    const float* kv   = (const float*)d_in[1];
    const int*   mask = (const int*)  d_in[2];
    const float* Wq   = (const float*)d_in[3];
    const float* bq   = (const float*)d_in[4];
    const float* Wk   = (const float*)d_in[5];
    const float* bk   = (const float*)d_in[6];
    const float* Wv   = (const float*)d_in[7];
    const float* bv   = (const float*)d_in[8];
    const float* Wo   = (const float*)d_in[9];
    const float* bo   = (const float*)d_in[10];
    const float* R    = (const float*)d_in[11];

    float* out = (float*)d_out;
    const size_t out_elems  = (size_t)BB*NQ*DM;
    const size_t attn_elems = (size_t)BHN*NQ*NKV;

    __nv_bfloat16 *Qhh, *Qhl, *Khh, *Khl, *Vhh, *Vhl, *Sb;
    __nv_bfloat16 *qh, *ql2, *kvh, *kvl, *ch, *cl, *Wh, *Wl;
    int *idxp, *cntp;
    float *attn_fb;
    cudaGetSymbolAddress((void**)&Qhh, g_Qhh);
    cudaGetSymbolAddress((void**)&Qhl, g_Qhl);
    cudaGetSymbolAddress((void**)&Khh, g_Khh);
    cudaGetSymbolAddress((void**)&Khl, g_Khl);
    cudaGetSymbolAddress((void**)&Vhh, g_Vhh);
    cudaGetSymbolAddress((void**)&Vhl, g_Vhl);
    cudaGetSymbolAddress((void**)&Sb,  g_Sb);
    cudaGetSymbolAddress((void**)&qh,  g_qh);
    cudaGetSymbolAddress((void**)&ql2, g_ql);
    cudaGetSymbolAddress((void**)&kvh, g_kvh);
    cudaGetSymbolAddress((void**)&kvl, g_kvl);
    cudaGetSymbolAddress((void**)&ch,  g_ch);
    cudaGetSymbolAddress((void**)&cl,  g_cl);
    cudaGetSymbolAddress((void**)&Wh,  g_Wh);
    cudaGetSymbolAddress((void**)&Wl,  g_Wl);
    cudaGetSymbolAddress((void**)&idxp, g_idx);
    cudaGetSymbolAddress((void**)&cntp, g_cnt);
    cudaGetSymbolAddress((void**)&attn_fb, g_attn_fallback);

    float* attn = ((size_t)out_size >= out_elems + attn_elems)
                ? (out + out_elems) : attn_fb;

    cudaFuncSetAttribute(proj_bf,  cudaFuncAttributeMaxDynamicSharedMemorySize, PROJB_SMEM);
    cudaFuncSetAttribute(bias_mma, cudaFuncAttributeMaxDynamicSharedMemorySize, BIAS_SMEM);
    cudaFuncSetAttribute(attn_mma, cudaFuncAttributeMaxDynamicSharedMemorySize, ATTN_SMEM);

    const size_t WSZ = (size_t)DM * DM;
    cvt_all<<<(2*N4_ACT + 4*N4_W) / 256, 256>>>(q, kv, Wq, Wk, Wv, Wo,
                                                qh, ql2, kvh, kvl, Wh, Wl);
    compact_mask<<<BB, 1024>>>(mask, idxp, cntp);

    dim3 gProj(4, 64);
    proj_bf<<<gProj, 256, PROJB_SMEM>>>(qh,  ql2, Wh + 0*WSZ, Wl + 0*WSZ, bq, nullptr, Qhh, Qhl, 1);
    proj_bf<<<gProj, 256, PROJB_SMEM>>>(kvh, kvl, Wh + 1*WSZ, Wl + 1*WSZ, bk, nullptr, Khh, Khl, 1);
    proj_bf<<<gProj, 256, PROJB_SMEM>>>(kvh, kvl, Wh + 2*WSZ, Wl + 2*WSZ, bv, nullptr, Vhh, Vhl, 1);

    bias_mma<<<dim3(2, 1024), 256, BIAS_SMEM>>>(Qhh, Qhl, R, Sb);

    attn_mma<<<dim3(64, 32), 512, ATTN_SMEM>>>(Qhh, Qhl, Khh, Khl, Vhh, Vhl,
                                               Sb, idxp, cntp, attn, ch, cl);

    proj_bf<<<gProj, 256, PROJB_SMEM>>>(ch, cl, Wh + 3*WSZ, Wl + 3*WSZ, bo, out, nullptr, nullptr, 0);
}